// round 1
// baseline (speedup 1.0000x reference)
#include <cuda_runtime.h>
#include <cstdint>

#define N_ROWS 8192
#define M_COLS 8192
#define D_DIM  128
#define BM 64
#define BN 64
#define WPR (M_COLS / 32)   // mask words per row = 256

// 8 MB scatter-mask bitmap (device global: no allocations allowed)
__device__ unsigned g_mask[N_ROWS * WPR];

__global__ void clear_mask_k() {
    const int total = N_ROWS * WPR;
    for (int i = blockIdx.x * blockDim.x + threadIdx.x; i < total;
         i += gridDim.x * blockDim.x)
        g_mask[i] = 0u;
}

__global__ void scatter_mask_k(const int* __restrict__ rows,
                               const int* __restrict__ cols, int n) {
    int i = blockIdx.x * blockDim.x + threadIdx.x;
    if (i < n) {
        unsigned r = (unsigned)rows[i];
        unsigned c = (unsigned)cols[i];
        atomicOr(&g_mask[r * WPR + (c >> 5)], 1u << (c & 31u));
    }
}

__device__ __forceinline__ float fexp2(float x) {
    float y;
    asm("ex2.approx.ftz.f32 %0, %1;" : "=f"(y) : "f"(x));
    return y;
}

// Shared memory layout (dynamic):
//   QsT [128][64]  (Q transposed: d-major for conflict-free fragment loads)
//   KsT [128][64]
//   Vs  [64][128]
//   Ps  [64][65]   (padded to kill column-access bank conflicts)
constexpr int SMEM_FLOATS = 128 * 64 * 3 + 64 * 65;
constexpr size_t SMEM_BYTES = SMEM_FLOATS * sizeof(float);

__global__ __launch_bounds__(256, 1)
void attn_k(const float* __restrict__ Q, const float* __restrict__ K,
            const float* __restrict__ V, float* __restrict__ Out) {
    extern __shared__ float smf[];
    float* QsT = smf;                 // [128][64]
    float* KsT = smf + 128 * 64;      // [128][64]
    float* Vs  = smf + 2 * 128 * 64;  // [64][128]
    float* Ps  = smf + 3 * 128 * 64;  // [64][65]

    const int tid = threadIdx.x;
    const int ty = tid >> 4;   // 0..15 -> 4 query rows each
    const int tx = tid & 15;   // 0..15 -> 4 score cols / 8 out cols each
    const int row0 = blockIdx.x * BM;

    // Load Q tile transposed: QsT[d][r]. r varies fastest over lanes so the
    // STS stream is conflict-free (stride-1 within each d-column).
    #pragma unroll
    for (int it = 0; it < 8; it++) {
        int idx = tid + it * 256;        // 2048 = 64 rows * 32 float4
        int r  = idx & 63;
        int c4 = idx >> 6;               // 0..31
        float4 q = *(const float4*)(Q + (size_t)(row0 + r) * D_DIM + c4 * 4);
        QsT[(c4 * 4 + 0) * 64 + r] = q.x;
        QsT[(c4 * 4 + 1) * 64 + r] = q.y;
        QsT[(c4 * 4 + 2) * 64 + r] = q.z;
        QsT[(c4 * 4 + 3) * 64 + r] = q.w;
    }

    float m_run[4], l_run[4], o_acc[4][8];
    #pragma unroll
    for (int i = 0; i < 4; i++) {
        m_run[i] = -1e30f;
        l_run[i] = 0.f;
        #pragma unroll
        for (int j = 0; j < 8; j++) o_acc[i][j] = 0.f;
    }

    // scale * log2(e): softmax done in base-2 domain, single MUFU.EX2 per score
    const float SC = 1.4426950408889634f * 0.08838834764831845f;

    for (int c0 = 0; c0 < M_COLS; c0 += BN) {
        __syncthreads();   // previous tile's Ps/Vs/KsT reads complete

        // Load K tile transposed + V tile row-major
        #pragma unroll
        for (int it = 0; it < 8; it++) {
            int idx = tid + it * 256;
            int r  = idx & 63;
            int c4 = idx >> 6;
            float4 k = *(const float4*)(K + (size_t)(c0 + r) * D_DIM + c4 * 4);
            KsT[(c4 * 4 + 0) * 64 + r] = k.x;
            KsT[(c4 * 4 + 1) * 64 + r] = k.y;
            KsT[(c4 * 4 + 2) * 64 + r] = k.z;
            KsT[(c4 * 4 + 3) * 64 + r] = k.w;
        }
        #pragma unroll
        for (int it = 0; it < 8; it++) {
            int idx = tid + it * 256;
            int r  = idx >> 5;
            int c4 = idx & 31;
            *(float4*)&Vs[r * 128 + c4 * 4] =
                *(const float4*)(V + (size_t)(c0 + r) * D_DIM + c4 * 4);
        }
        __syncthreads();

        // ---- S = Q @ K^T (4x4 per thread, d-major fragments) ----
        float s[4][4];
        #pragma unroll
        for (int i = 0; i < 4; i++)
            #pragma unroll
            for (int j = 0; j < 4; j++) s[i][j] = 0.f;

        #pragma unroll 8
        for (int d = 0; d < D_DIM; d++) {
            float4 a = *(const float4*)&QsT[d * 64 + ty * 4];
            float4 b = *(const float4*)&KsT[d * 64 + tx * 4];
            s[0][0] += a.x * b.x; s[0][1] += a.x * b.y; s[0][2] += a.x * b.z; s[0][3] += a.x * b.w;
            s[1][0] += a.y * b.x; s[1][1] += a.y * b.y; s[1][2] += a.y * b.z; s[1][3] += a.y * b.w;
            s[2][0] += a.z * b.x; s[2][1] += a.z * b.y; s[2][2] += a.z * b.z; s[2][3] += a.z * b.w;
            s[3][0] += a.w * b.x; s[3][1] += a.w * b.y; s[3][2] += a.w * b.z; s[3][3] += a.w * b.w;
        }

        // ---- mask + online softmax ----
        const int wcol   = (c0 >> 5) + (tx >> 3);   // word covering cols c0+tx*4..+3
        const int bshift = (tx * 4) & 31;

        #pragma unroll
        for (int i = 0; i < 4; i++) {
            unsigned mw = g_mask[(size_t)(row0 + ty * 4 + i) * WPR + wcol] >> bshift;
            float sv[4];
            float smax = -1e30f;
            #pragma unroll
            for (int j = 0; j < 4; j++) {
                float v = ((mw >> j) & 1u) ? -1e30f : s[i][j] * SC;
                sv[j] = v;
                smax = fmaxf(smax, v);
            }
            #pragma unroll
            for (int off = 8; off; off >>= 1)
                smax = fmaxf(smax, __shfl_xor_sync(0xffffffffu, smax, off, 16));

            float mn    = fmaxf(m_run[i], smax);
            float alpha = fexp2(m_run[i] - mn);
            m_run[i] = mn;

            float lt = 0.f;
            #pragma unroll
            for (int j = 0; j < 4; j++) {
                float p = fexp2(sv[j] - mn);
                Ps[(ty * 4 + i) * 65 + tx * 4 + j] = p;
                lt += p;
            }
            #pragma unroll
            for (int off = 8; off; off >>= 1)
                lt += __shfl_xor_sync(0xffffffffu, lt, off, 16);

            l_run[i] = l_run[i] * alpha + lt;
            #pragma unroll
            for (int j = 0; j < 8; j++) o_acc[i][j] *= alpha;
        }

        __syncthreads();   // Ps fully written

        // ---- O += P @ V (4 rows x 8 cols per thread) ----
        #pragma unroll 4
        for (int j = 0; j < BN; j++) {
            float4 v0 = *(const float4*)&Vs[j * 128 + tx * 8];
            float4 v1 = *(const float4*)&Vs[j * 128 + tx * 8 + 4];
            #pragma unroll
            for (int i = 0; i < 4; i++) {
                float p = Ps[(ty * 4 + i) * 65 + j];
                o_acc[i][0] += p * v0.x; o_acc[i][1] += p * v0.y;
                o_acc[i][2] += p * v0.z; o_acc[i][3] += p * v0.w;
                o_acc[i][4] += p * v1.x; o_acc[i][5] += p * v1.y;
                o_acc[i][6] += p * v1.z; o_acc[i][7] += p * v1.w;
            }
        }
    }

    // ---- finalize: O / l ----
    #pragma unroll
    for (int i = 0; i < 4; i++) {
        float inv = 1.f / l_run[i];
        float4 r0 = make_float4(o_acc[i][0] * inv, o_acc[i][1] * inv,
                                o_acc[i][2] * inv, o_acc[i][3] * inv);
        float4 r1 = make_float4(o_acc[i][4] * inv, o_acc[i][5] * inv,
                                o_acc[i][6] * inv, o_acc[i][7] * inv);
        float* dst = Out + (size_t)(row0 + ty * 4 + i) * D_DIM + tx * 8;
        *(float4*)dst       = r0;
        *(float4*)(dst + 4) = r1;
    }
}

extern "C" void kernel_launch(void* const* d_in, const int* in_sizes, int n_in,
                              void* d_out, int out_size) {
    const float* Q  = (const float*)d_in[0];
    const float* K  = (const float*)d_in[1];
    const float* V  = (const float*)d_in[2];
    const int*   mr = (const int*)d_in[3];
    const int*   mc = (const int*)d_in[4];
    const int nmask = in_sizes[3];
    float* Out = (float*)d_out;

    cudaFuncSetAttribute(attn_k, cudaFuncAttributeMaxDynamicSharedMemorySize,
                         (int)SMEM_BYTES);

    clear_mask_k<<<256, 256>>>();
    scatter_mask_k<<<(nmask + 255) / 256, 256>>>(mr, mc, nmask);
    attn_k<<<N_ROWS / BM, 256, SMEM_BYTES>>>(Q, K, V, Out);
}

// round 4
// speedup vs baseline: 4.5238x; 4.5238x over previous
#include <cuda_runtime.h>
#include <cuda_bf16.h>
#include <cstdint>

#define NQ 8192
#define MK 8192
#define DD 128
#define WPR 256            // mask words per row
#define BM 128
#define BN 64
#define SPLITS 2
#define CPS (MK / SPLITS)  // 4096 cols per split
#define TT (CPS / BN)      // 64 tiles per CTA

// ---------------- device globals (no allocations allowed) ----------------
__device__ __align__(16) unsigned g_mask[NQ * WPR];                   // 8 MB bitmap
__device__ __align__(256) __nv_bfloat16 g_qhi[NQ * DD], g_qlo[NQ * DD];
__device__ __align__(256) __nv_bfloat16 g_khi[MK * DD], g_klo[MK * DD];
__device__ __align__(256) __nv_bfloat16 g_vthi[DD * MK], g_vtlo[DD * MK]; // V transposed [d][m]
__device__ __align__(16) float g_opart[SPLITS * NQ * DD];             // unnormalized partial O
__device__ __align__(16) float g_lpart[SPLITS * NQ];                  // partial softmax sums

// ---------------- helpers ----------------
__device__ __forceinline__ uint32_t smem_u32(const void* p) {
    uint32_t a;
    asm("{ .reg .u64 t; cvta.to.shared.u64 t, %1; cvt.u32.u64 %0, t; }" : "=r"(a) : "l"(p));
    return a;
}
__device__ __forceinline__ float fexp2(float x) {
    float y; asm("ex2.approx.ftz.f32 %0, %1;" : "=f"(y) : "f"(x)); return y;
}
__device__ __forceinline__ void cp_async16(uint32_t dst, const void* src) {
    asm volatile("cp.async.cg.shared.global [%0], [%1], 16;" :: "r"(dst), "l"(src) : "memory");
}
#define CP_COMMIT()   asm volatile("cp.async.commit_group;" ::: "memory")
#define CP_WAIT_1()   asm volatile("cp.async.wait_group 1;" ::: "memory")

__device__ __forceinline__ void ldsm4(uint32_t& r0, uint32_t& r1, uint32_t& r2, uint32_t& r3,
                                      uint32_t a) {
    asm volatile("ldmatrix.sync.aligned.m8n8.x4.shared.b16 {%0,%1,%2,%3}, [%4];"
                 : "=r"(r0), "=r"(r1), "=r"(r2), "=r"(r3) : "r"(a));
}
__device__ __forceinline__ void mma16816(float* c, uint32_t a0, uint32_t a1, uint32_t a2,
                                         uint32_t a3, uint32_t b0, uint32_t b1) {
    asm volatile("mma.sync.aligned.m16n8k16.row.col.f32.bf16.bf16.f32 "
                 "{%0,%1,%2,%3}, {%4,%5,%6,%7}, {%8,%9}, {%0,%1,%2,%3};"
                 : "+f"(c[0]), "+f"(c[1]), "+f"(c[2]), "+f"(c[3])
                 : "r"(a0), "r"(a1), "r"(a2), "r"(a3), "r"(b0), "r"(b1));
}
__device__ __forceinline__ uint32_t pack_bf2(float x, float y) {
    __nv_bfloat16 hx = __float2bfloat16(x), hy = __float2bfloat16(y);
    return (uint32_t)__bfloat16_as_ushort(hx) | ((uint32_t)__bfloat16_as_ushort(hy) << 16);
}

// ---------------- aux kernels ----------------
__global__ void clear_mask_k() {
    const int total = NQ * WPR;
    for (int i = blockIdx.x * blockDim.x + threadIdx.x; i < total; i += gridDim.x * blockDim.x)
        g_mask[i] = 0u;
}
__global__ void scatter_mask_k(const int* __restrict__ rows, const int* __restrict__ cols, int n) {
    int i = blockIdx.x * blockDim.x + threadIdx.x;
    if (i < n) {
        unsigned r = (unsigned)rows[i], c = (unsigned)cols[i];
        atomicOr(&g_mask[r * WPR + (c >> 5)], 1u << (c & 31u));
    }
}
__global__ void convert_k(const float* __restrict__ Q, const float* __restrict__ K,
                          const float* __restrict__ V) {
    int i = blockIdx.x * blockDim.x + threadIdx.x;
    if (i >= NQ * DD) return;
    float q = Q[i];
    __nv_bfloat16 h = __float2bfloat16(q);
    g_qhi[i] = h; g_qlo[i] = __float2bfloat16(q - __bfloat162float(h));
    float k = K[i];
    h = __float2bfloat16(k);
    g_khi[i] = h; g_klo[i] = __float2bfloat16(k - __bfloat162float(h));
    float v = V[i];
    int r = i >> 7, c = i & 127;
    h = __float2bfloat16(v);
    g_vthi[c * MK + r] = h;
    g_vtlo[c * MK + r] = __float2bfloat16(v - __bfloat162float(h));
}
__global__ void combine_k(float* __restrict__ out) {
    int i = blockIdx.x * blockDim.x + threadIdx.x;  // float4 index
    if (i >= NQ * DD / 4) return;
    int row = i >> 5;
    float inv = 1.f / (g_lpart[row] + g_lpart[NQ + row]);
    float4 a = *(const float4*)&g_opart[i * 4];
    float4 b = *(const float4*)&g_opart[NQ * DD + i * 4];
    float4 o = make_float4((a.x + b.x) * inv, (a.y + b.y) * inv,
                           (a.z + b.z) * inv, (a.w + b.w) * inv);
    *(float4*)&out[i * 4] = o;
}

// ---------------- main attention kernel (warp mma.sync) ----------------
// dyn smem layout (bytes from 1024-aligned base):
//   Qhi [128 rows][256B, chunk-swizzled]  @ 0      (32 KB)
//   Qlo                                   @ 32768  (32 KB)
//   buf b @ 65536 + b*65536:  Khi(16K) Klo(16K) Vthi(16K) Vtlo(16K)
#define Q_HI 0
#define Q_LO 32768
#define BUF0 65536
#define BUFSZ 65536
constexpr size_t SMEM_BYTES = 197632;   // 1024 pad + 64K Q + 2*64K KV bufs

__device__ __forceinline__ void load_kv_tile(uint32_t buf, int c0, int tid) {
    // K hi/lo: 64 rows x 16 chunks(16B), swizzled chunk = cc ^ (r&7)
    #pragma unroll
    for (int i = 0; i < 4; i++) {
        int w = tid + i * 256;
        int r = w >> 4, cc = w & 15;
        cp_async16(buf + r * 256 + ((cc ^ (r & 7)) << 4),
                   g_khi + (size_t)(c0 + r) * DD + cc * 8);
    }
    #pragma unroll
    for (int i = 0; i < 4; i++) {
        int w = tid + i * 256;
        int r = w >> 4, cc = w & 15;
        cp_async16(buf + 16384 + r * 256 + ((cc ^ (r & 7)) << 4),
                   g_klo + (size_t)(c0 + r) * DD + cc * 8);
    }
    // Vt hi/lo: 128 rows(d) x 8 chunks, swizzle cc ^ (d&7)
    #pragma unroll
    for (int i = 0; i < 4; i++) {
        int w = tid + i * 256;
        int d = w >> 3, cc = w & 7;
        cp_async16(buf + 32768 + d * 128 + ((cc ^ (d & 7)) << 4),
                   g_vthi + (size_t)d * MK + c0 + cc * 8);
    }
    #pragma unroll
    for (int i = 0; i < 4; i++) {
        int w = tid + i * 256;
        int d = w >> 3, cc = w & 7;
        cp_async16(buf + 49152 + d * 128 + ((cc ^ (d & 7)) << 4),
                   g_vtlo + (size_t)d * MK + c0 + cc * 8);
    }
}

__global__ __launch_bounds__(256, 1)
void attn_mma_k() {
    extern __shared__ char smdyn[];
    uint32_t smd = (smem_u32(smdyn) + 1023u) & ~1023u;

    const int tid = threadIdx.x;
    const int wp = tid >> 5;
    const int lane = tid & 31;
    const int g = lane >> 2, tt = lane & 3;
    const int m4 = lane >> 3;       // ldmatrix matrix group 0..3
    const int l7 = lane & 7;

    const int row_blk = blockIdx.x >> 1;
    const int split = blockIdx.x & 1;
    const int row0 = row_blk * BM;
    const int cbase = split * CPS;

    // ---- prologue: Q tile + first two KV tiles via cp.async ----
    #pragma unroll
    for (int i = 0; i < 8; i++) {
        int w = tid + i * 256;
        int r = w >> 4, cc = w & 15;
        cp_async16(smd + Q_HI + r * 256 + ((cc ^ (r & 7)) << 4),
                   g_qhi + (size_t)(row0 + r) * DD + cc * 8);
    }
    #pragma unroll
    for (int i = 0; i < 8; i++) {
        int w = tid + i * 256;
        int r = w >> 4, cc = w & 15;
        cp_async16(smd + Q_LO + r * 256 + ((cc ^ (r & 7)) << 4),
                   g_qlo + (size_t)(row0 + r) * DD + cc * 8);
    }
    load_kv_tile(smd + BUF0, cbase, tid);
    CP_COMMIT();                                     // group: Q + tile0
    load_kv_tile(smd + BUF0 + BUFSZ, cbase + BN, tid);
    CP_COMMIT();                                     // group: tile1

    // per-lane ldmatrix address components
    const int a_row = wp * 16 + ((m4 & 1) << 3) + l7;        // Q rows for A frags
    const uint32_t a_hi = smd + Q_HI + a_row * 256;
    const uint32_t a_lo = smd + Q_LO + a_row * 256;
    const int a_sw = a_row & 7;
    const int a_ms = m4 >> 1;                                 // chunk select (k-half)
    const int b_rb = ((m4 >> 1) << 3) + l7;                   // B row base within tile
    const int b_sw = b_rb & 7;
    const int b_ms = m4 & 1;

    float oa[16][4];
    #pragma unroll
    for (int i = 0; i < 16; i++)
        #pragma unroll
        for (int j = 0; j < 4; j++) oa[i][j] = 0.f;
    float l0 = 0.f, l1 = 0.f;

    const float SC = 0.12753102694653973f;  // log2(e)/sqrt(128)
    const unsigned* mrow = g_mask + (size_t)(row0 + wp * 16 + g) * WPR + (cbase >> 5);

    for (int t = 0; t < TT; t++) {
        const uint32_t buf = smd + BUF0 + (t & 1) * BUFSZ;
        CP_WAIT_1();
        __syncthreads();

        // ---- S = Qhi*Khi + Qhi*Klo + Qlo*Khi  (per warp: 16 x 64) ----
        float sc[8][4];
        #pragma unroll
        for (int i = 0; i < 8; i++)
            #pragma unroll
            for (int j = 0; j < 4; j++) sc[i][j] = 0.f;

        const uint32_t kh = buf, kl = buf + 16384;
        #pragma unroll
        for (int kc = 0; kc < 8; kc++) {
            uint32_t ah0, ah1, ah2, ah3, al0, al1, al2, al3;
            uint32_t choA = (uint32_t)(((2 * kc + a_ms) ^ a_sw) << 4);
            ldsm4(ah0, ah1, ah2, ah3, a_hi + choA);
            ldsm4(al0, al1, al2, al3, a_lo + choA);
            uint32_t choB = (uint32_t)(((2 * kc + b_ms) ^ b_sw) << 4);
            #pragma unroll
            for (int jp = 0; jp < 4; jp++) {
                uint32_t roff = (uint32_t)((jp * 16 + b_rb) * 256) + choB;
                uint32_t bh0, bh1, bh2, bh3, bl0, bl1, bl2, bl3;
                ldsm4(bh0, bh1, bh2, bh3, kh + roff);
                ldsm4(bl0, bl1, bl2, bl3, kl + roff);
                mma16816(sc[2 * jp],     ah0, ah1, ah2, ah3, bh0, bh1);
                mma16816(sc[2 * jp + 1], ah0, ah1, ah2, ah3, bh2, bh3);
                mma16816(sc[2 * jp],     ah0, ah1, ah2, ah3, bl0, bl1);
                mma16816(sc[2 * jp + 1], ah0, ah1, ah2, ah3, bl2, bl3);
                mma16816(sc[2 * jp],     al0, al1, al2, al3, bh0, bh1);
                mma16816(sc[2 * jp + 1], al0, al1, al2, al3, bh2, bh3);
            }
        }

        // ---- mask + exp2 + split P into bf16 hi/lo A-fragments ----
        uint2 mw0 = *(const uint2*)(mrow + t * 2);
        uint2 mw1 = *(const uint2*)(mrow + 8 * WPR + t * 2);
        uint32_t ph[4][4], pl[4][4];
        #pragma unroll
        for (int j = 0; j < 8; j++) {
            unsigned w0 = (j < 4) ? mw0.x : mw0.y;
            unsigned w1 = (j < 4) ? mw1.x : mw1.y;
            int sh = (j & 3) * 8 + 2 * tt;
            float p00 = ((w0 >> sh) & 1u)       ? 0.f : fexp2(sc[j][0] * SC);
            float p01 = ((w0 >> (sh + 1)) & 1u) ? 0.f : fexp2(sc[j][1] * SC);
            float p10 = ((w1 >> sh) & 1u)       ? 0.f : fexp2(sc[j][2] * SC);
            float p11 = ((w1 >> (sh + 1)) & 1u) ? 0.f : fexp2(sc[j][3] * SC);
            l0 += p00 + p01;
            l1 += p10 + p11;
            uint32_t h0 = pack_bf2(p00, p01);
            uint32_t h1 = pack_bf2(p10, p11);
            float r00 = p00 - __bfloat162float(__ushort_as_bfloat16((unsigned short)(h0 & 0xffff)));
            float r01 = p01 - __bfloat162float(__ushort_as_bfloat16((unsigned short)(h0 >> 16)));
            float r10 = p10 - __bfloat162float(__ushort_as_bfloat16((unsigned short)(h1 & 0xffff)));
            float r11 = p11 - __bfloat162float(__ushort_as_bfloat16((unsigned short)(h1 >> 16)));
            int kc2 = j >> 1, hs = (j & 1) * 2;
            ph[kc2][hs]     = h0;
            ph[kc2][hs + 1] = h1;
            pl[kc2][hs]     = pack_bf2(r00, r01);
            pl[kc2][hs + 1] = pack_bf2(r10, r11);
        }

        // ---- O += Phi*Vhi + Phi*Vlo + Plo*Vhi  (per warp: 16 x 128) ----
        const uint32_t vh = buf + 32768, vl = buf + 49152;
        #pragma unroll
        for (int kc2 = 0; kc2 < 4; kc2++) {
            uint32_t cho = (uint32_t)(((2 * kc2 + b_ms) ^ b_sw) << 4);
            #pragma unroll
            for (int p = 0; p < 8; p++) {
                uint32_t roff = (uint32_t)((p * 16 + b_rb) * 128) + cho;
                uint32_t vh0, vh1, vh2, vh3, vl0, vl1, vl2, vl3;
                ldsm4(vh0, vh1, vh2, vh3, vh + roff);
                ldsm4(vl0, vl1, vl2, vl3, vl + roff);
                mma16816(oa[2 * p],     ph[kc2][0], ph[kc2][1], ph[kc2][2], ph[kc2][3], vh0, vh1);
                mma16816(oa[2 * p + 1], ph[kc2][0], ph[kc2][1], ph[kc2][2], ph[kc2][3], vh2, vh3);
                mma16816(oa[2 * p],     ph[kc2][0], ph[kc2][1], ph[kc2][2], ph[kc2][3], vl0, vl1);
                mma16816(oa[2 * p + 1], ph[kc2][0], ph[kc2][1], ph[kc2][2], ph[kc2][3], vl2, vl3);
                mma16816(oa[2 * p],     pl[kc2][0], pl[kc2][1], pl[kc2][2], pl[kc2][3], vh0, vh1);
                mma16816(oa[2 * p + 1], pl[kc2][0], pl[kc2][1], pl[kc2][2], pl[kc2][3], vh2, vh3);
            }
        }

        __syncthreads();   // all warps done reading buf before refill
        if (t + 2 < TT)
            load_kv_tile(buf, cbase + (t + 2) * BN, tid);
        CP_COMMIT();       // (possibly empty group keeps wait_group(1) semantics)
    }

    // ---- reduce l across the 4 lanes of each row group ----
    #pragma unroll
    for (int off = 1; off < 4; off <<= 1) {
        l0 += __shfl_xor_sync(0xffffffffu, l0, off);
        l1 += __shfl_xor_sync(0xffffffffu, l1, off);
    }

    // ---- store unnormalized partial O + l ----
    {
        const int r0g = row0 + wp * 16 + g;
        float* op0 = g_opart + ((size_t)split * NQ + r0g) * DD;
        float* op1 = op0 + 8 * DD;
        #pragma unroll
        for (int dn = 0; dn < 16; dn++) {
            *(float2*)(op0 + dn * 8 + 2 * tt) = make_float2(oa[dn][0], oa[dn][1]);
            *(float2*)(op1 + dn * 8 + 2 * tt) = make_float2(oa[dn][2], oa[dn][3]);
        }
        if (tt == 0) {
            g_lpart[(size_t)split * NQ + r0g] = l0;
            g_lpart[(size_t)split * NQ + r0g + 8] = l1;
        }
    }
}

// ---------------- launcher ----------------
extern "C" void kernel_launch(void* const* d_in, const int* in_sizes, int n_in,
                              void* d_out, int out_size) {
    const float* Q  = (const float*)d_in[0];
    const float* K  = (const float*)d_in[1];
    const float* V  = (const float*)d_in[2];
    const int*   mr = (const int*)d_in[3];
    const int*   mc = (const int*)d_in[4];
    const int nmask = in_sizes[3];
    float* Out = (float*)d_out;

    cudaFuncSetAttribute(attn_mma_k, cudaFuncAttributeMaxDynamicSharedMemorySize,
                         (int)SMEM_BYTES);

    clear_mask_k<<<512, 256>>>();
    scatter_mask_k<<<(nmask + 255) / 256, 256>>>(mr, mc, nmask);
    convert_k<<<(NQ * DD + 255) / 256, 256>>>(Q, K, V);
    attn_mma_k<<<(NQ / BM) * SPLITS, 256, SMEM_BYTES>>>();
    combine_k<<<(NQ * DD / 4 + 255) / 256, 256>>>(Out);
}

// round 5
// speedup vs baseline: 6.6034x; 1.4597x over previous
#include <cuda_runtime.h>
#include <cuda_fp16.h>
#include <cstdint>

#define NQ 8192
#define MK 8192
#define DD 128
#define WPR 256            // mask words per row
#define BM 128
#define BN 64
#define SPLITS 2
#define CPS (MK / SPLITS)  // 4096 cols per split
#define TT (CPS / BN)      // 64 tiles per CTA

// ---------------- device globals (no allocations allowed) ----------------
__device__ __align__(16) unsigned g_mask[NQ * WPR];                   // 8 MB bitmap
__device__ __align__(256) __half g_qhi[NQ * DD], g_qlo[NQ * DD];
__device__ __align__(256) __half g_khi[MK * DD], g_klo[MK * DD];
__device__ __align__(256) __half g_vt[DD * MK];                       // V transposed [d][m], fp16
__device__ __align__(16) float g_opart[SPLITS * NQ * DD];             // unnormalized partial O
__device__ __align__(16) float g_lpart[SPLITS * NQ];                  // partial softmax sums

// ---------------- helpers ----------------
__device__ __forceinline__ uint32_t smem_u32(const void* p) {
    uint32_t a;
    asm("{ .reg .u64 t; cvta.to.shared.u64 t, %1; cvt.u32.u64 %0, t; }" : "=r"(a) : "l"(p));
    return a;
}
__device__ __forceinline__ float fexp2(float x) {
    float y; asm("ex2.approx.ftz.f32 %0, %1;" : "=f"(y) : "f"(x)); return y;
}
__device__ __forceinline__ void cp_async16(uint32_t dst, const void* src) {
    asm volatile("cp.async.cg.shared.global [%0], [%1], 16;" :: "r"(dst), "l"(src) : "memory");
}
#define CP_COMMIT()   asm volatile("cp.async.commit_group;" ::: "memory")
#define CP_WAIT_1()   asm volatile("cp.async.wait_group 1;" ::: "memory")

__device__ __forceinline__ void ldsm4(uint32_t& r0, uint32_t& r1, uint32_t& r2, uint32_t& r3,
                                      uint32_t a) {
    asm volatile("ldmatrix.sync.aligned.m8n8.x4.shared.b16 {%0,%1,%2,%3}, [%4];"
                 : "=r"(r0), "=r"(r1), "=r"(r2), "=r"(r3) : "r"(a));
}
__device__ __forceinline__ void mma16816(float* c, uint32_t a0, uint32_t a1, uint32_t a2,
                                         uint32_t a3, uint32_t b0, uint32_t b1) {
    asm volatile("mma.sync.aligned.m16n8k16.row.col.f32.f16.f16.f32 "
                 "{%0,%1,%2,%3}, {%4,%5,%6,%7}, {%8,%9}, {%0,%1,%2,%3};"
                 : "+f"(c[0]), "+f"(c[1]), "+f"(c[2]), "+f"(c[3])
                 : "r"(a0), "r"(a1), "r"(a2), "r"(a3), "r"(b0), "r"(b1));
}

// ---------------- aux kernels ----------------
__global__ void clear_mask_k() {
    const int total = NQ * WPR;
    for (int i = blockIdx.x * blockDim.x + threadIdx.x; i < total; i += gridDim.x * blockDim.x)
        g_mask[i] = 0u;
}
__global__ void scatter_mask_k(const int* __restrict__ rows, const int* __restrict__ cols, int n) {
    int i = blockIdx.x * blockDim.x + threadIdx.x;
    if (i < n) {
        unsigned r = (unsigned)rows[i], c = (unsigned)cols[i];
        atomicOr(&g_mask[r * WPR + (c >> 5)], 1u << (c & 31u));
    }
}
__global__ void convert_k(const float* __restrict__ Q, const float* __restrict__ K,
                          const float* __restrict__ V) {
    int i = blockIdx.x * blockDim.x + threadIdx.x;
    if (i >= NQ * DD) return;
    float q = Q[i];
    __half h = __float2half_rn(q);
    g_qhi[i] = h; g_qlo[i] = __float2half_rn(q - __half2float(h));
    float k = K[i];
    h = __float2half_rn(k);
    g_khi[i] = h; g_klo[i] = __float2half_rn(k - __half2float(h));
    float v = V[i];
    int r = i >> 7, c = i & 127;
    g_vt[c * MK + r] = __float2half_rn(v);
}
__global__ void combine_k(float* __restrict__ out) {
    int i = blockIdx.x * blockDim.x + threadIdx.x;  // float4 index
    if (i >= NQ * DD / 4) return;
    int row = i >> 5;
    float inv = 1.f / (g_lpart[row] + g_lpart[NQ + row]);
    float4 a = *(const float4*)&g_opart[i * 4];
    float4 b = *(const float4*)&g_opart[NQ * DD + i * 4];
    float4 o = make_float4((a.x + b.x) * inv, (a.y + b.y) * inv,
                           (a.z + b.z) * inv, (a.w + b.w) * inv);
    *(float4*)&out[i * 4] = o;
}

// ---------------- main attention kernel (warp mma.sync, fp16 split) ----------------
// dyn smem (from 1024-aligned base):
//   Qhi [128 rows][256B, chunk-swizzled]  @ 0      (32 KB)
//   Qlo                                   @ 32768  (32 KB)
//   buf b @ 65536 + b*49152:  Khi(16K) Klo(16K) Vt(16K)
#define Q_HI 0
#define Q_LO 32768
#define BUF0 65536
#define BUFSZ 49152
constexpr size_t SMEM_BYTES = 164864;   // 1024 pad + 64K Q + 2*48K KV bufs

__device__ __forceinline__ void load_kv_tile(uint32_t buf, int c0, int tid) {
    // K hi/lo: 64 rows x 16 chunks(16B), swizzled chunk = cc ^ (r&7)
    #pragma unroll
    for (int i = 0; i < 4; i++) {
        int w = tid + i * 256;
        int r = w >> 4, cc = w & 15;
        cp_async16(buf + r * 256 + ((cc ^ (r & 7)) << 4),
                   g_khi + (size_t)(c0 + r) * DD + cc * 8);
    }
    #pragma unroll
    for (int i = 0; i < 4; i++) {
        int w = tid + i * 256;
        int r = w >> 4, cc = w & 15;
        cp_async16(buf + 16384 + r * 256 + ((cc ^ (r & 7)) << 4),
                   g_klo + (size_t)(c0 + r) * DD + cc * 8);
    }
    // Vt: 128 rows(d) x 8 chunks, swizzle cc ^ (d&7)
    #pragma unroll
    for (int i = 0; i < 4; i++) {
        int w = tid + i * 256;
        int d = w >> 3, cc = w & 7;
        cp_async16(buf + 32768 + d * 128 + ((cc ^ (d & 7)) << 4),
                   g_vt + (size_t)d * MK + c0 + cc * 8);
    }
}

__global__ __launch_bounds__(256, 1)
void attn_mma_k() {
    extern __shared__ char smdyn[];
    uint32_t smd = (smem_u32(smdyn) + 1023u) & ~1023u;

    const int tid = threadIdx.x;
    const int wp = tid >> 5;
    const int lane = tid & 31;
    const int g = lane >> 2, tt = lane & 3;
    const int m4 = lane >> 3;       // ldmatrix matrix group 0..3
    const int l7 = lane & 7;

    const int row_blk = blockIdx.x >> 1;
    const int split = blockIdx.x & 1;
    const int row0 = row_blk * BM;
    const int cbase = split * CPS;

    // ---- prologue: Q tile + first two KV tiles via cp.async ----
    #pragma unroll
    for (int i = 0; i < 8; i++) {
        int w = tid + i * 256;
        int r = w >> 4, cc = w & 15;
        cp_async16(smd + Q_HI + r * 256 + ((cc ^ (r & 7)) << 4),
                   g_qhi + (size_t)(row0 + r) * DD + cc * 8);
    }
    #pragma unroll
    for (int i = 0; i < 8; i++) {
        int w = tid + i * 256;
        int r = w >> 4, cc = w & 15;
        cp_async16(smd + Q_LO + r * 256 + ((cc ^ (r & 7)) << 4),
                   g_qlo + (size_t)(row0 + r) * DD + cc * 8);
    }
    load_kv_tile(smd + BUF0, cbase, tid);
    CP_COMMIT();                                     // group: Q + tile0
    load_kv_tile(smd + BUF0 + BUFSZ, cbase + BN, tid);
    CP_COMMIT();                                     // group: tile1

    // per-lane ldmatrix address components
    const int a_row = wp * 16 + ((m4 & 1) << 3) + l7;        // Q rows for A frags
    const uint32_t a_hi = smd + Q_HI + a_row * 256;
    const uint32_t a_lo = smd + Q_LO + a_row * 256;
    const int a_sw = a_row & 7;
    const int a_ms = m4 >> 1;                                 // chunk select (k-half)
    const int b_rb = ((m4 >> 1) << 3) + l7;                   // B row base within tile
    const int b_sw = b_rb & 7;
    const int b_ms = m4 & 1;

    float oa[16][4];
    #pragma unroll
    for (int i = 0; i < 16; i++)
        #pragma unroll
        for (int j = 0; j < 4; j++) oa[i][j] = 0.f;
    float l0 = 0.f, l1 = 0.f;

    const float SC = 0.12753102694653973f;  // log2(e)/sqrt(128)
    const unsigned* mrow = g_mask + (size_t)(row0 + wp * 16 + g) * WPR + (cbase >> 5);

    for (int t = 0; t < TT; t++) {
        const uint32_t buf = smd + BUF0 + (t & 1) * BUFSZ;
        CP_WAIT_1();
        __syncthreads();

        // prefetch mask words early: LDG latency hides under the S MMAs
        uint2 mw0 = *(const uint2*)(mrow + t * 2);
        uint2 mw1 = *(const uint2*)(mrow + 8 * WPR + t * 2);

        // ---- S = Qhi*Khi + Qhi*Klo + Qlo*Khi  (per warp: 16 x 64) ----
        float sc[8][4];
        #pragma unroll
        for (int i = 0; i < 8; i++)
            #pragma unroll
            for (int j = 0; j < 4; j++) sc[i][j] = 0.f;

        const uint32_t kh = buf, kl = buf + 16384;
        #pragma unroll
        for (int kc = 0; kc < 8; kc++) {
            uint32_t ah0, ah1, ah2, ah3, al0, al1, al2, al3;
            uint32_t choA = (uint32_t)(((2 * kc + a_ms) ^ a_sw) << 4);
            ldsm4(ah0, ah1, ah2, ah3, a_hi + choA);
            ldsm4(al0, al1, al2, al3, a_lo + choA);
            uint32_t choB = (uint32_t)(((2 * kc + b_ms) ^ b_sw) << 4);
            #pragma unroll
            for (int jp = 0; jp < 4; jp++) {
                uint32_t roff = (uint32_t)((jp * 16 + b_rb) * 256) + choB;
                uint32_t bh0, bh1, bh2, bh3, bl0, bl1, bl2, bl3;
                ldsm4(bh0, bh1, bh2, bh3, kh + roff);
                ldsm4(bl0, bl1, bl2, bl3, kl + roff);
                mma16816(sc[2 * jp],     ah0, ah1, ah2, ah3, bh0, bh1);
                mma16816(sc[2 * jp + 1], ah0, ah1, ah2, ah3, bh2, bh3);
                mma16816(sc[2 * jp],     ah0, ah1, ah2, ah3, bl0, bl1);
                mma16816(sc[2 * jp + 1], ah0, ah1, ah2, ah3, bl2, bl3);
                mma16816(sc[2 * jp],     al0, al1, al2, al3, bh0, bh1);
                mma16816(sc[2 * jp + 1], al0, al1, al2, al3, bh2, bh3);
            }
        }

        // ---- mask + exp2 + pack P into fp16 A-fragments (single precision pass) ----
        uint32_t ph[4][4];
        #pragma unroll
        for (int j = 0; j < 8; j++) {
            unsigned w0 = (j < 4) ? mw0.x : mw0.y;
            unsigned w1 = (j < 4) ? mw1.x : mw1.y;
            int sh = (j & 3) * 8 + 2 * tt;
            float p00 = ((w0 >> sh) & 1u)       ? 0.f : fexp2(sc[j][0] * SC);
            float p01 = ((w0 >> (sh + 1)) & 1u) ? 0.f : fexp2(sc[j][1] * SC);
            float p10 = ((w1 >> sh) & 1u)       ? 0.f : fexp2(sc[j][2] * SC);
            float p11 = ((w1 >> (sh + 1)) & 1u) ? 0.f : fexp2(sc[j][3] * SC);
            l0 += p00 + p01;
            l1 += p10 + p11;
            __half2 h0 = __floats2half2_rn(p00, p01);
            __half2 h1 = __floats2half2_rn(p10, p11);
            int kc2 = j >> 1, hs = (j & 1) * 2;
            ph[kc2][hs]     = *(uint32_t*)&h0;
            ph[kc2][hs + 1] = *(uint32_t*)&h1;
        }

        // ---- O += P*V  (per warp: 16 x 128, single fp16 pass) ----
        const uint32_t vh = buf + 32768;
        #pragma unroll
        for (int kc2 = 0; kc2 < 4; kc2++) {
            uint32_t cho = (uint32_t)(((2 * kc2 + b_ms) ^ b_sw) << 4);
            #pragma unroll
            for (int p = 0; p < 8; p++) {
                uint32_t roff = (uint32_t)((p * 16 + b_rb) * 128) + cho;
                uint32_t vh0, vh1, vh2, vh3;
                ldsm4(vh0, vh1, vh2, vh3, vh + roff);
                mma16816(oa[2 * p],     ph[kc2][0], ph[kc2][1], ph[kc2][2], ph[kc2][3], vh0, vh1);
                mma16816(oa[2 * p + 1], ph[kc2][0], ph[kc2][1], ph[kc2][2], ph[kc2][3], vh2, vh3);
            }
        }

        __syncthreads();   // all warps done reading buf before refill
        if (t + 2 < TT)
            load_kv_tile(buf, cbase + (t + 2) * BN, tid);
        CP_COMMIT();       // (possibly empty group keeps wait_group(1) semantics)
    }

    // ---- reduce l across the 4 lanes of each row group ----
    #pragma unroll
    for (int off = 1; off < 4; off <<= 1) {
        l0 += __shfl_xor_sync(0xffffffffu, l0, off);
        l1 += __shfl_xor_sync(0xffffffffu, l1, off);
    }

    // ---- store unnormalized partial O + l ----
    {
        const int r0g = row0 + wp * 16 + g;
        float* op0 = g_opart + ((size_t)split * NQ + r0g) * DD;
        float* op1 = op0 + 8 * DD;
        #pragma unroll
        for (int dn = 0; dn < 16; dn++) {
            *(float2*)(op0 + dn * 8 + 2 * tt) = make_float2(oa[dn][0], oa[dn][1]);
            *(float2*)(op1 + dn * 8 + 2 * tt) = make_float2(oa[dn][2], oa[dn][3]);
        }
        if (tt == 0) {
            g_lpart[(size_t)split * NQ + r0g] = l0;
            g_lpart[(size_t)split * NQ + r0g + 8] = l1;
        }
    }
}

// ---------------- launcher ----------------
extern "C" void kernel_launch(void* const* d_in, const int* in_sizes, int n_in,
                              void* d_out, int out_size) {
    const float* Q  = (const float*)d_in[0];
    const float* K  = (const float*)d_in[1];
    const float* V  = (const float*)d_in[2];
    const int*   mr = (const int*)d_in[3];
    const int*   mc = (const int*)d_in[4];
    const int nmask = in_sizes[3];
    float* Out = (float*)d_out;

    cudaFuncSetAttribute(attn_mma_k, cudaFuncAttributeMaxDynamicSharedMemorySize,
                         (int)SMEM_BYTES);

    clear_mask_k<<<512, 256>>>();
    scatter_mask_k<<<(nmask + 255) / 256, 256>>>(mr, mc, nmask);
    convert_k<<<(NQ * DD + 255) / 256, 256>>>(Q, K, V);
    attn_mma_k<<<(NQ / BM) * SPLITS, 256, SMEM_BYTES>>>();
    combine_k<<<(NQ * DD / 4 + 255) / 256, 256>>>(Out);
}

// round 6
// speedup vs baseline: 7.1837x; 1.0879x over previous
#include <cuda_runtime.h>
#include <cuda_fp16.h>
#include <cstdint>

#define NQ 8192
#define MK 8192
#define DD 128
#define WPR 256            // mask words per row
#define BM 128
#define BN 64
#define SPLITS 2
#define CPS (MK / SPLITS)  // 4096 cols per split
#define TT (CPS / BN)      // 64 tiles per CTA

// ---------------- device globals (no allocations allowed) ----------------
__device__ __align__(16) unsigned g_mask[NQ * WPR];                   // 8 MB bitmap
__device__ __align__(256) __half g_qhi[NQ * DD];
__device__ __align__(256) __half g_khi[MK * DD], g_klo[MK * DD];
__device__ __align__(256) __half g_vt[DD * MK];                       // V transposed [d][m]
__device__ __align__(16) float g_opart[SPLITS * NQ * DD];             // unnormalized partial O
__device__ __align__(16) float g_lpart[SPLITS * NQ];                  // partial softmax sums

// ---------------- helpers ----------------
__device__ __forceinline__ uint32_t smem_u32(const void* p) {
    uint32_t a;
    asm("{ .reg .u64 t; cvta.to.shared.u64 t, %1; cvt.u32.u64 %0, t; }" : "=r"(a) : "l"(p));
    return a;
}
__device__ __forceinline__ float fexp2(float x) {
    float y; asm("ex2.approx.ftz.f32 %0, %1;" : "=f"(y) : "f"(x)); return y;
}
__device__ __forceinline__ void cp_async16(uint32_t dst, const void* src) {
    asm volatile("cp.async.cg.shared.global [%0], [%1], 16;" :: "r"(dst), "l"(src) : "memory");
}
#define CP_COMMIT()   asm volatile("cp.async.commit_group;" ::: "memory")
#define CP_WAIT_1()   asm volatile("cp.async.wait_group 1;" ::: "memory")

__device__ __forceinline__ void ldsm4(uint32_t& r0, uint32_t& r1, uint32_t& r2, uint32_t& r3,
                                      uint32_t a) {
    asm volatile("ldmatrix.sync.aligned.m8n8.x4.shared.b16 {%0,%1,%2,%3}, [%4];"
                 : "=r"(r0), "=r"(r1), "=r"(r2), "=r"(r3) : "r"(a));
}
__device__ __forceinline__ void mma16816(float* c, uint32_t a0, uint32_t a1, uint32_t a2,
                                         uint32_t a3, uint32_t b0, uint32_t b1) {
    asm volatile("mma.sync.aligned.m16n8k16.row.col.f32.f16.f16.f32 "
                 "{%0,%1,%2,%3}, {%4,%5,%6,%7}, {%8,%9}, {%0,%1,%2,%3};"
                 : "+f"(c[0]), "+f"(c[1]), "+f"(c[2]), "+f"(c[3])
                 : "r"(a0), "r"(a1), "r"(a2), "r"(a3), "r"(b0), "r"(b1));
}

// ---------------- aux kernels ----------------
__global__ void clear_mask_k() {
    const int total = NQ * WPR;
    for (int i = blockIdx.x * blockDim.x + threadIdx.x; i < total; i += gridDim.x * blockDim.x)
        g_mask[i] = 0u;
}
__global__ void scatter_mask_k(const int* __restrict__ rows, const int* __restrict__ cols, int n) {
    int i = blockIdx.x * blockDim.x + threadIdx.x;
    if (i < n) {
        unsigned r = (unsigned)rows[i], c = (unsigned)cols[i];
        atomicOr(&g_mask[r * WPR + (c >> 5)], 1u << (c & 31u));
    }
}
__global__ void convert_k(const float* __restrict__ Q, const float* __restrict__ K,
                          const float* __restrict__ V) {
    int i = blockIdx.x * blockDim.x + threadIdx.x;
    if (i >= NQ * DD) return;
    g_qhi[i] = __float2half_rn(Q[i]);
    float k = K[i];
    __half h = __float2half_rn(k);
    g_khi[i] = h; g_klo[i] = __float2half_rn(k - __half2float(h));
    int r = i >> 7, c = i & 127;
    g_vt[c * MK + r] = __float2half_rn(V[i]);
}
__global__ void combine_k(float* __restrict__ out) {
    int i = blockIdx.x * blockDim.x + threadIdx.x;  // float4 index
    if (i >= NQ * DD / 4) return;
    int row = i >> 5;
    float inv = 1.f / (g_lpart[row] + g_lpart[NQ + row]);
    float4 a = *(const float4*)&g_opart[i * 4];
    float4 b = *(const float4*)&g_opart[NQ * DD + i * 4];
    float4 o = make_float4((a.x + b.x) * inv, (a.y + b.y) * inv,
                           (a.z + b.z) * inv, (a.w + b.w) * inv);
    *(float4*)&out[i * 4] = o;
}

// ---------------- main attention kernel (warp mma.sync, fp16) ----------------
// dyn smem (from 1024-aligned base):
//   Qhi [128 rows][256B, chunk-swizzled]  @ 0      (32 KB)
//   buf b (b=0..2) @ 32768 + b*49152:  Khi(16K) Klo(16K) Vt(16K)
#define Q_HI 0
#define BUF0 32768
#define BUFSZ 49152
constexpr size_t SMEM_BYTES = 1024 + 32768 + 3 * 49152;   // 181248

__device__ __forceinline__ void load_kv_tile(uint32_t buf, int c0, int tid) {
    // K hi/lo: 64 rows x 16 chunks(16B), swizzled chunk = cc ^ (r&7)
    #pragma unroll
    for (int i = 0; i < 4; i++) {
        int w = tid + i * 256;
        int r = w >> 4, cc = w & 15;
        cp_async16(buf + r * 256 + ((cc ^ (r & 7)) << 4),
                   g_khi + (size_t)(c0 + r) * DD + cc * 8);
    }
    #pragma unroll
    for (int i = 0; i < 4; i++) {
        int w = tid + i * 256;
        int r = w >> 4, cc = w & 15;
        cp_async16(buf + 16384 + r * 256 + ((cc ^ (r & 7)) << 4),
                   g_klo + (size_t)(c0 + r) * DD + cc * 8);
    }
    // Vt: 128 rows(d) x 8 chunks, swizzle cc ^ (d&7)
    #pragma unroll
    for (int i = 0; i < 4; i++) {
        int w = tid + i * 256;
        int d = w >> 3, cc = w & 7;
        cp_async16(buf + 32768 + d * 128 + ((cc ^ (d & 7)) << 4),
                   g_vt + (size_t)d * MK + c0 + cc * 8);
    }
}

__global__ __launch_bounds__(256, 1)
void attn_mma_k() {
    extern __shared__ char smdyn[];
    uint32_t smd = (smem_u32(smdyn) + 1023u) & ~1023u;

    const int tid = threadIdx.x;
    const int wp = tid >> 5;
    const int lane = tid & 31;
    const int g = lane >> 2, tt = lane & 3;
    const int m4 = lane >> 3;       // ldmatrix matrix group 0..3
    const int l7 = lane & 7;

    const int row_blk = blockIdx.x >> 1;
    const int split = blockIdx.x & 1;
    const int row0 = row_blk * BM;
    const int cbase = split * CPS;

    // ---- prologue: Q tile + first two KV tiles via cp.async ----
    #pragma unroll
    for (int i = 0; i < 8; i++) {
        int w = tid + i * 256;
        int r = w >> 4, cc = w & 15;
        cp_async16(smd + Q_HI + r * 256 + ((cc ^ (r & 7)) << 4),
                   g_qhi + (size_t)(row0 + r) * DD + cc * 8);
    }
    load_kv_tile(smd + BUF0, cbase, tid);
    CP_COMMIT();                                     // group: Q + tile0
    load_kv_tile(smd + BUF0 + BUFSZ, cbase + BN, tid);
    CP_COMMIT();                                     // group: tile1

    // per-lane ldmatrix address components
    const int a_row = wp * 16 + ((m4 & 1) << 3) + l7;        // Q rows for A frags
    const uint32_t a_hi = smd + Q_HI + a_row * 256;
    const int a_sw = a_row & 7;
    const int a_ms = m4 >> 1;                                 // chunk select (k-half)
    const int b_rb = ((m4 >> 1) << 3) + l7;                   // B row base within tile
    const int b_sw = b_rb & 7;
    const int b_ms = m4 & 1;

    float oa[16][4];
    #pragma unroll
    for (int i = 0; i < 16; i++)
        #pragma unroll
        for (int j = 0; j < 4; j++) oa[i][j] = 0.f;
    float l0 = 0.f, l1 = 0.f;

    const float SC = 0.12753102694653973f;  // log2(e)/sqrt(128)
    const unsigned* mrow = g_mask + (size_t)(row0 + wp * 16 + g) * WPR + (cbase >> 5);

    for (int t = 0; t < TT; t++) {
        // buf index cycles 0,1,2; tile t lives in buf[t % 3]
        const int bi = t % 3;
        const uint32_t buf = smd + BUF0 + bi * BUFSZ;

        CP_WAIT_1();       // tile t complete (t+1 may still be in flight)
        __syncthreads();   // all warps done with tile t-1 -> its buffer is free

        // refill: tile t+2 into buf[(t+2)%3] (== buf of tile t-1)
        if (t + 2 < TT) {
            load_kv_tile(smd + BUF0 + ((t + 2) % 3) * BUFSZ, cbase + (t + 2) * BN, tid);
        }
        CP_COMMIT();

        // prefetch mask words: LDG latency hides under the S MMAs
        uint2 mw0 = *(const uint2*)(mrow + t * 2);
        uint2 mw1 = *(const uint2*)(mrow + 8 * WPR + t * 2);

        // ---- S = Qhi*Khi + Qhi*Klo = Qhi*K  (per warp: 16 x 64) ----
        float sc[8][4];
        #pragma unroll
        for (int i = 0; i < 8; i++)
            #pragma unroll
            for (int j = 0; j < 4; j++) sc[i][j] = 0.f;

        const uint32_t kh = buf, kl = buf + 16384;
        #pragma unroll
        for (int kc = 0; kc < 8; kc++) {
            uint32_t ah0, ah1, ah2, ah3;
            uint32_t choA = (uint32_t)(((2 * kc + a_ms) ^ a_sw) << 4);
            ldsm4(ah0, ah1, ah2, ah3, a_hi + choA);
            uint32_t choB = (uint32_t)(((2 * kc + b_ms) ^ b_sw) << 4);
            #pragma unroll
            for (int jp = 0; jp < 4; jp++) {
                uint32_t roff = (uint32_t)((jp * 16 + b_rb) * 256) + choB;
                uint32_t bh0, bh1, bh2, bh3, bl0, bl1, bl2, bl3;
                ldsm4(bh0, bh1, bh2, bh3, kh + roff);
                ldsm4(bl0, bl1, bl2, bl3, kl + roff);
                mma16816(sc[2 * jp],     ah0, ah1, ah2, ah3, bh0, bh1);
                mma16816(sc[2 * jp + 1], ah0, ah1, ah2, ah3, bh2, bh3);
                mma16816(sc[2 * jp],     ah0, ah1, ah2, ah3, bl0, bl1);
                mma16816(sc[2 * jp + 1], ah0, ah1, ah2, ah3, bl2, bl3);
            }
        }

        // ---- mask + exp2 + pack P into fp16 A-fragments ----
        uint32_t ph[4][4];
        #pragma unroll
        for (int j = 0; j < 8; j++) {
            unsigned w0 = (j < 4) ? mw0.x : mw0.y;
            unsigned w1 = (j < 4) ? mw1.x : mw1.y;
            int sh = (j & 3) * 8 + 2 * tt;
            float p00 = ((w0 >> sh) & 1u)       ? 0.f : fexp2(sc[j][0] * SC);
            float p01 = ((w0 >> (sh + 1)) & 1u) ? 0.f : fexp2(sc[j][1] * SC);
            float p10 = ((w1 >> sh) & 1u)       ? 0.f : fexp2(sc[j][2] * SC);
            float p11 = ((w1 >> (sh + 1)) & 1u) ? 0.f : fexp2(sc[j][3] * SC);
            l0 += p00 + p01;
            l1 += p10 + p11;
            __half2 h0 = __floats2half2_rn(p00, p01);
            __half2 h1 = __floats2half2_rn(p10, p11);
            int kc2 = j >> 1, hs = (j & 1) * 2;
            ph[kc2][hs]     = *(uint32_t*)&h0;
            ph[kc2][hs + 1] = *(uint32_t*)&h1;
        }

        // ---- O += P*V  (per warp: 16 x 128) ----
        const uint32_t vh = buf + 32768;
        #pragma unroll
        for (int kc2 = 0; kc2 < 4; kc2++) {
            uint32_t cho = (uint32_t)(((2 * kc2 + b_ms) ^ b_sw) << 4);
            #pragma unroll
            for (int p = 0; p < 8; p++) {
                uint32_t roff = (uint32_t)((p * 16 + b_rb) * 128) + cho;
                uint32_t vh0, vh1, vh2, vh3;
                ldsm4(vh0, vh1, vh2, vh3, vh + roff);
                mma16816(oa[2 * p],     ph[kc2][0], ph[kc2][1], ph[kc2][2], ph[kc2][3], vh0, vh1);
                mma16816(oa[2 * p + 1], ph[kc2][0], ph[kc2][1], ph[kc2][2], ph[kc2][3], vh2, vh3);
            }
        }
    }

    // ---- reduce l across the 4 lanes of each row group ----
    #pragma unroll
    for (int off = 1; off < 4; off <<= 1) {
        l0 += __shfl_xor_sync(0xffffffffu, l0, off);
        l1 += __shfl_xor_sync(0xffffffffu, l1, off);
    }

    // ---- store unnormalized partial O + l ----
    {
        const int r0g = row0 + wp * 16 + g;
        float* op0 = g_opart + ((size_t)split * NQ + r0g) * DD;
        float* op1 = op0 + 8 * DD;
        #pragma unroll
        for (int dn = 0; dn < 16; dn++) {
            *(float2*)(op0 + dn * 8 + 2 * tt) = make_float2(oa[dn][0], oa[dn][1]);
            *(float2*)(op1 + dn * 8 + 2 * tt) = make_float2(oa[dn][2], oa[dn][3]);
        }
        if (tt == 0) {
            g_lpart[(size_t)split * NQ + r0g] = l0;
            g_lpart[(size_t)split * NQ + r0g + 8] = l1;
        }
    }
}

// ---------------- launcher ----------------
extern "C" void kernel_launch(void* const* d_in, const int* in_sizes, int n_in,
                              void* d_out, int out_size) {
    const float* Q  = (const float*)d_in[0];
    const float* K  = (const float*)d_in[1];
    const float* V  = (const float*)d_in[2];
    const int*   mr = (const int*)d_in[3];
    const int*   mc = (const int*)d_in[4];
    const int nmask = in_sizes[3];
    float* Out = (float*)d_out;

    cudaFuncSetAttribute(attn_mma_k, cudaFuncAttributeMaxDynamicSharedMemorySize,
                         (int)SMEM_BYTES);

    clear_mask_k<<<512, 256>>>();
    scatter_mask_k<<<(nmask + 255) / 256, 256>>>(mr, mc, nmask);
    convert_k<<<(NQ * DD + 255) / 256, 256>>>(Q, K, V);
    attn_mma_k<<<(NQ / BM) * SPLITS, 256, SMEM_BYTES>>>();
    combine_k<<<(NQ * DD / 4 + 255) / 256, 256>>>(Out);
}

// round 7
// speedup vs baseline: 7.4581x; 1.0382x over previous
#include <cuda_runtime.h>
#include <cuda_fp16.h>
#include <cstdint>

#define NQ 8192
#define MK 8192
#define DD 128
#define WPR 256            // mask words per row
#define BM 128
#define BN 64
#define SPLITS 2
#define CPS (MK / SPLITS)  // 4096 cols per split
#define TT (CPS / BN)      // 64 tiles per CTA

// ---------------- device globals (no allocations allowed) ----------------
__device__ __align__(16) unsigned g_mask[NQ * WPR];                   // 8 MB bitmap
__device__ __align__(256) __half g_qhi[NQ * DD];
__device__ __align__(256) __half g_khi[MK * DD], g_klo[MK * DD];
__device__ __align__(256) __half g_vt[DD * MK];                       // V transposed [d][m]
__device__ __align__(16) float g_opart[SPLITS * NQ * DD];             // unnormalized partial O
__device__ __align__(16) float g_lpart[SPLITS * NQ];                  // partial softmax sums

// ---------------- helpers ----------------
__device__ __forceinline__ uint32_t smem_u32(const void* p) {
    uint32_t a;
    asm("{ .reg .u64 t; cvta.to.shared.u64 t, %1; cvt.u32.u64 %0, t; }" : "=r"(a) : "l"(p));
    return a;
}
__device__ __forceinline__ float fexp2(float x) {
    float y; asm("ex2.approx.ftz.f32 %0, %1;" : "=f"(y) : "f"(x)); return y;
}
__device__ __forceinline__ void cp_async16(uint32_t dst, const void* src) {
    asm volatile("cp.async.cg.shared.global [%0], [%1], 16;" :: "r"(dst), "l"(src) : "memory");
}
#define CP_COMMIT()   asm volatile("cp.async.commit_group;" ::: "memory")
#define CP_WAIT_1()   asm volatile("cp.async.wait_group 1;" ::: "memory")

__device__ __forceinline__ void ldsm4(uint32_t& r0, uint32_t& r1, uint32_t& r2, uint32_t& r3,
                                      uint32_t a) {
    asm volatile("ldmatrix.sync.aligned.m8n8.x4.shared.b16 {%0,%1,%2,%3}, [%4];"
                 : "=r"(r0), "=r"(r1), "=r"(r2), "=r"(r3) : "r"(a));
}
__device__ __forceinline__ void mma16816(float* c, uint32_t a0, uint32_t a1, uint32_t a2,
                                         uint32_t a3, uint32_t b0, uint32_t b1) {
    asm volatile("mma.sync.aligned.m16n8k16.row.col.f32.f16.f16.f32 "
                 "{%0,%1,%2,%3}, {%4,%5,%6,%7}, {%8,%9}, {%0,%1,%2,%3};"
                 : "+f"(c[0]), "+f"(c[1]), "+f"(c[2]), "+f"(c[3])
                 : "r"(a0), "r"(a1), "r"(a2), "r"(a3), "r"(b0), "r"(b1));
}

// ---------------- aux kernels ----------------
__global__ void clear_mask_k() {
    const int total = NQ * WPR;
    for (int i = blockIdx.x * blockDim.x + threadIdx.x; i < total; i += gridDim.x * blockDim.x)
        g_mask[i] = 0u;
}
__global__ void scatter_mask_k(const int* __restrict__ rows, const int* __restrict__ cols, int n) {
    int i = blockIdx.x * blockDim.x + threadIdx.x;
    if (i < n) {
        unsigned r = (unsigned)rows[i], c = (unsigned)cols[i];
        atomicOr(&g_mask[r * WPR + (c >> 5)], 1u << (c & 31u));
    }
}
__global__ void convert_k(const float* __restrict__ Q, const float* __restrict__ K,
                          const float* __restrict__ V) {
    int i = blockIdx.x * blockDim.x + threadIdx.x;
    if (i >= NQ * DD) return;
    g_qhi[i] = __float2half_rn(Q[i]);
    float k = K[i];
    __half h = __float2half_rn(k);
    g_khi[i] = h; g_klo[i] = __float2half_rn(k - __half2float(h));
    int r = i >> 7, c = i & 127;
    g_vt[c * MK + r] = __float2half_rn(V[i]);
}
__global__ void combine_k(float* __restrict__ out) {
    int i = blockIdx.x * blockDim.x + threadIdx.x;  // float4 index
    if (i >= NQ * DD / 4) return;
    int row = i >> 5;
    float inv = 1.f / (g_lpart[row] + g_lpart[NQ + row]);
    float4 a = *(const float4*)&g_opart[i * 4];
    float4 b = *(const float4*)&g_opart[NQ * DD + i * 4];
    float4 o = make_float4((a.x + b.x) * inv, (a.y + b.y) * inv,
                           (a.z + b.z) * inv, (a.w + b.w) * inv);
    *(float4*)&out[i * 4] = o;
}

// ---------------- main attention kernel (warp mma.sync, fp16, SW-pipelined) ----------------
// dyn smem (from 1024-aligned base):
//   Qhi [128 rows][256B, chunk-swizzled]  @ 0      (32 KB)
//   buf b (b=0..2) @ 32768 + b*49152:  Khi(16K) Klo(16K) Vt(16K)
#define Q_HI 0
#define BUF0 32768
#define BUFSZ 49152
constexpr size_t SMEM_BYTES = 1024 + 32768 + 3 * 49152;   // 181248

__device__ __forceinline__ void load_kv_tile(uint32_t buf, int c0, int tid) {
    #pragma unroll
    for (int i = 0; i < 4; i++) {
        int w = tid + i * 256;
        int r = w >> 4, cc = w & 15;
        cp_async16(buf + r * 256 + ((cc ^ (r & 7)) << 4),
                   g_khi + (size_t)(c0 + r) * DD + cc * 8);
    }
    #pragma unroll
    for (int i = 0; i < 4; i++) {
        int w = tid + i * 256;
        int r = w >> 4, cc = w & 15;
        cp_async16(buf + 16384 + r * 256 + ((cc ^ (r & 7)) << 4),
                   g_klo + (size_t)(c0 + r) * DD + cc * 8);
    }
    #pragma unroll
    for (int i = 0; i < 4; i++) {
        int w = tid + i * 256;
        int d = w >> 3, cc = w & 7;
        cp_async16(buf + 32768 + d * 128 + ((cc ^ (d & 7)) << 4),
                   g_vt + (size_t)d * MK + c0 + cc * 8);
    }
}

// issue the 16x64 S-tile MMAs (Qhi*Khi + Qhi*Klo) into sc
__device__ __forceinline__ void issue_S(float sc[8][4], uint32_t buf, uint32_t a_hi,
                                        int a_sw, int a_ms, int b_rb, int b_sw, int b_ms) {
    #pragma unroll
    for (int i = 0; i < 8; i++)
        #pragma unroll
        for (int j = 0; j < 4; j++) sc[i][j] = 0.f;
    const uint32_t kh = buf, kl = buf + 16384;
    #pragma unroll
    for (int kc = 0; kc < 8; kc++) {
        uint32_t ah0, ah1, ah2, ah3;
        uint32_t choA = (uint32_t)(((2 * kc + a_ms) ^ a_sw) << 4);
        ldsm4(ah0, ah1, ah2, ah3, a_hi + choA);
        uint32_t choB = (uint32_t)(((2 * kc + b_ms) ^ b_sw) << 4);
        #pragma unroll
        for (int jp = 0; jp < 4; jp++) {
            uint32_t roff = (uint32_t)((jp * 16 + b_rb) * 256) + choB;
            uint32_t bh0, bh1, bh2, bh3, bl0, bl1, bl2, bl3;
            ldsm4(bh0, bh1, bh2, bh3, kh + roff);
            ldsm4(bl0, bl1, bl2, bl3, kl + roff);
            mma16816(sc[2 * jp],     ah0, ah1, ah2, ah3, bh0, bh1);
            mma16816(sc[2 * jp + 1], ah0, ah1, ah2, ah3, bh2, bh3);
            mma16816(sc[2 * jp],     ah0, ah1, ah2, ah3, bl0, bl1);
            mma16816(sc[2 * jp + 1], ah0, ah1, ah2, ah3, bl2, bl3);
        }
    }
}

__global__ __launch_bounds__(256, 1)
void attn_mma_k() {
    extern __shared__ char smdyn[];
    uint32_t smd = (smem_u32(smdyn) + 1023u) & ~1023u;

    const int tid = threadIdx.x;
    const int wp = tid >> 5;
    const int lane = tid & 31;
    const int g = lane >> 2, tt = lane & 3;
    const int m4 = lane >> 3;
    const int l7 = lane & 7;

    const int row_blk = blockIdx.x >> 1;
    const int split = blockIdx.x & 1;
    const int row0 = row_blk * BM;
    const int cbase = split * CPS;

    // ---- prologue: Q tile + first two KV tiles via cp.async ----
    #pragma unroll
    for (int i = 0; i < 8; i++) {
        int w = tid + i * 256;
        int r = w >> 4, cc = w & 15;
        cp_async16(smd + Q_HI + r * 256 + ((cc ^ (r & 7)) << 4),
                   g_qhi + (size_t)(row0 + r) * DD + cc * 8);
    }
    load_kv_tile(smd + BUF0, cbase, tid);
    CP_COMMIT();                                     // G0: Q + tile0
    load_kv_tile(smd + BUF0 + BUFSZ, cbase + BN, tid);
    CP_COMMIT();                                     // G1: tile1

    // per-lane ldmatrix address components
    const int a_row = wp * 16 + ((m4 & 1) << 3) + l7;
    const uint32_t a_hi = smd + Q_HI + a_row * 256;
    const int a_sw = a_row & 7;
    const int a_ms = m4 >> 1;
    const int b_rb = ((m4 >> 1) << 3) + l7;
    const int b_sw = b_rb & 7;
    const int b_ms = m4 & 1;

    float oa[16][4];
    #pragma unroll
    for (int i = 0; i < 16; i++)
        #pragma unroll
        for (int j = 0; j < 4; j++) oa[i][j] = 0.f;
    float l0 = 0.f, l1 = 0.f;

    const float SC = 0.12753102694653973f;  // log2(e)/sqrt(128)
    const unsigned* mrow = g_mask + (size_t)(row0 + wp * 16 + g) * WPR + (cbase >> 5);

    // S double buffer (sw-pipeline across tiles)
    float sc[2][8][4];

    // ---- issue S(0): needs Q + tile0 (group G0 done after wait_1) ----
    CP_WAIT_1();
    __syncthreads();
    issue_S(sc[0], smd + BUF0, a_hi, a_sw, a_ms, b_rb, b_sw, b_ms);

    #pragma unroll 2
    for (int t = 0; t < TT; t++) {
        const uint32_t buf_t = smd + BUF0 + (t % 3) * BUFSZ;

        // prefetch mask words: LDG latency hides under MMA issue
        uint2 mw0 = *(const uint2*)(mrow + t * 2);
        uint2 mw1 = *(const uint2*)(mrow + 8 * WPR + t * 2);

        // barrier: all warps are past PV(t-1) -> buf[(t+2)%3] (== buf[t-1]) is free
        __syncthreads();
        if (t + 2 < TT)
            load_kv_tile(smd + BUF0 + ((t + 2) % 3) * BUFSZ, cbase + (t + 2) * BN, tid);
        CP_COMMIT();       // always commit (possibly empty) to keep the group window

        // ---- issue S(t+1) BEFORE softmax(t): tensor pipe stays fed ----
        if (t + 1 < TT) {
            CP_WAIT_1();   // pending <= 1 (the group just committed) => tile t+1 resident
            issue_S(sc[(t + 1) & 1], smd + BUF0 + ((t + 1) % 3) * BUFSZ,
                    a_hi, a_sw, a_ms, b_rb, b_sw, b_ms);
        }

        // ---- softmax(t): mask + exp2 + pack fp16 A-fragments ----
        float (*scc)[4] = sc[t & 1];
        uint32_t ph[4][4];
        #pragma unroll
        for (int j = 0; j < 8; j++) {
            unsigned w0 = (j < 4) ? mw0.x : mw0.y;
            unsigned w1 = (j < 4) ? mw1.x : mw1.y;
            int sh = (j & 3) * 8 + 2 * tt;
            float p00 = ((w0 >> sh) & 1u)       ? 0.f : fexp2(scc[j][0] * SC);
            float p01 = ((w0 >> (sh + 1)) & 1u) ? 0.f : fexp2(scc[j][1] * SC);
            float p10 = ((w1 >> sh) & 1u)       ? 0.f : fexp2(scc[j][2] * SC);
            float p11 = ((w1 >> (sh + 1)) & 1u) ? 0.f : fexp2(scc[j][3] * SC);
            l0 += p00 + p01;
            l1 += p10 + p11;
            __half2 h0 = __floats2half2_rn(p00, p01);
            __half2 h1 = __floats2half2_rn(p10, p11);
            int kc2 = j >> 1, hs = (j & 1) * 2;
            ph[kc2][hs]     = *(uint32_t*)&h0;
            ph[kc2][hs + 1] = *(uint32_t*)&h1;
        }

        // ---- O += P*V(t) ----
        const uint32_t vh = buf_t + 32768;
        #pragma unroll
        for (int kc2 = 0; kc2 < 4; kc2++) {
            uint32_t cho = (uint32_t)(((2 * kc2 + b_ms) ^ b_sw) << 4);
            #pragma unroll
            for (int p = 0; p < 8; p++) {
                uint32_t roff = (uint32_t)((p * 16 + b_rb) * 128) + cho;
                uint32_t vh0, vh1, vh2, vh3;
                ldsm4(vh0, vh1, vh2, vh3, vh + roff);
                mma16816(oa[2 * p],     ph[kc2][0], ph[kc2][1], ph[kc2][2], ph[kc2][3], vh0, vh1);
                mma16816(oa[2 * p + 1], ph[kc2][0], ph[kc2][1], ph[kc2][2], ph[kc2][3], vh2, vh3);
            }
        }
    }

    // ---- reduce l across the 4 lanes of each row group ----
    #pragma unroll
    for (int off = 1; off < 4; off <<= 1) {
        l0 += __shfl_xor_sync(0xffffffffu, l0, off);
        l1 += __shfl_xor_sync(0xffffffffu, l1, off);
    }

    // ---- store unnormalized partial O + l ----
    {
        const int r0g = row0 + wp * 16 + g;
        float* op0 = g_opart + ((size_t)split * NQ + r0g) * DD;
        float* op1 = op0 + 8 * DD;
        #pragma unroll
        for (int dn = 0; dn < 16; dn++) {
            *(float2*)(op0 + dn * 8 + 2 * tt) = make_float2(oa[dn][0], oa[dn][1]);
            *(float2*)(op1 + dn * 8 + 2 * tt) = make_float2(oa[dn][2], oa[dn][3]);
        }
        if (tt == 0) {
            g_lpart[(size_t)split * NQ + r0g] = l0;
            g_lpart[(size_t)split * NQ + r0g + 8] = l1;
        }
    }
}

// ---------------- launcher ----------------
extern "C" void kernel_launch(void* const* d_in, const int* in_sizes, int n_in,
                              void* d_out, int out_size) {
    const float* Q  = (const float*)d_in[0];
    const float* K  = (const float*)d_in[1];
    const float* V  = (const float*)d_in[2];
    const int*   mr = (const int*)d_in[3];
    const int*   mc = (const int*)d_in[4];
    const int nmask = in_sizes[3];
    float* Out = (float*)d_out;

    cudaFuncSetAttribute(attn_mma_k, cudaFuncAttributeMaxDynamicSharedMemorySize,
                         (int)SMEM_BYTES);

    clear_mask_k<<<512, 256>>>();
    scatter_mask_k<<<(nmask + 255) / 256, 256>>>(mr, mc, nmask);
    convert_k<<<(NQ * DD + 255) / 256, 256>>>(Q, K, V);
    attn_mma_k<<<(NQ / BM) * SPLITS, 256, SMEM_BYTES>>>();
    combine_k<<<(NQ * DD / 4 + 255) / 256, 256>>>(Out);
}

// round 8
// speedup vs baseline: 7.5509x; 1.0125x over previous
#include <cuda_runtime.h>
#include <cuda_fp16.h>
#include <cstdint>

#define NQ 8192
#define MK 8192
#define DD 128
#define WPR 256            // mask words per row
#define BM 64
#define BN 64
#define SPLITS 2
#define CPS (MK / SPLITS)  // 4096 cols per split
#define TT (CPS / BN)      // 64 tiles per CTA
#define THREADS 128

// ---------------- device globals (no allocations allowed) ----------------
__device__ __align__(16) unsigned g_mask[NQ * WPR];                   // 8 MB bitmap
__device__ __align__(256) __half g_qhi[NQ * DD];
__device__ __align__(256) __half g_khi[MK * DD], g_klo[MK * DD];
__device__ __align__(256) __half g_vt[DD * MK];                       // V transposed [d][m]
__device__ __align__(16) float g_opart[SPLITS * NQ * DD];             // unnormalized partial O
__device__ __align__(16) float g_lpart[SPLITS * NQ];                  // partial softmax sums

// ---------------- helpers ----------------
__device__ __forceinline__ uint32_t smem_u32(const void* p) {
    uint32_t a;
    asm("{ .reg .u64 t; cvta.to.shared.u64 t, %1; cvt.u32.u64 %0, t; }" : "=r"(a) : "l"(p));
    return a;
}
__device__ __forceinline__ float fexp2(float x) {
    float y; asm("ex2.approx.ftz.f32 %0, %1;" : "=f"(y) : "f"(x)); return y;
}
__device__ __forceinline__ void cp_async16(uint32_t dst, const void* src) {
    asm volatile("cp.async.cg.shared.global [%0], [%1], 16;" :: "r"(dst), "l"(src) : "memory");
}
#define CP_COMMIT()   asm volatile("cp.async.commit_group;" ::: "memory")
#define CP_WAIT_1()   asm volatile("cp.async.wait_group 1;" ::: "memory")

__device__ __forceinline__ void ldsm4(uint32_t& r0, uint32_t& r1, uint32_t& r2, uint32_t& r3,
                                      uint32_t a) {
    asm volatile("ldmatrix.sync.aligned.m8n8.x4.shared.b16 {%0,%1,%2,%3}, [%4];"
                 : "=r"(r0), "=r"(r1), "=r"(r2), "=r"(r3) : "r"(a));
}
__device__ __forceinline__ void mma16816(float* c, uint32_t a0, uint32_t a1, uint32_t a2,
                                         uint32_t a3, uint32_t b0, uint32_t b1) {
    asm volatile("mma.sync.aligned.m16n8k16.row.col.f32.f16.f16.f32 "
                 "{%0,%1,%2,%3}, {%4,%5,%6,%7}, {%8,%9}, {%0,%1,%2,%3};"
                 : "+f"(c[0]), "+f"(c[1]), "+f"(c[2]), "+f"(c[3])
                 : "r"(a0), "r"(a1), "r"(a2), "r"(a3), "r"(b0), "r"(b1));
}

// ---------------- aux kernels ----------------
__global__ void clear_mask_k() {
    const int total = NQ * WPR;
    for (int i = blockIdx.x * blockDim.x + threadIdx.x; i < total; i += gridDim.x * blockDim.x)
        g_mask[i] = 0u;
}
__global__ void scatter_mask_k(const int* __restrict__ rows, const int* __restrict__ cols, int n) {
    int i = blockIdx.x * blockDim.x + threadIdx.x;
    if (i < n) {
        unsigned r = (unsigned)rows[i], c = (unsigned)cols[i];
        atomicOr(&g_mask[r * WPR + (c >> 5)], 1u << (c & 31u));
    }
}
__global__ void convert_k(const float* __restrict__ Q, const float* __restrict__ K,
                          const float* __restrict__ V) {
    int i = blockIdx.x * blockDim.x + threadIdx.x;
    if (i >= NQ * DD) return;
    g_qhi[i] = __float2half_rn(Q[i]);
    float k = K[i];
    __half h = __float2half_rn(k);
    g_khi[i] = h; g_klo[i] = __float2half_rn(k - __half2float(h));
    int r = i >> 7, c = i & 127;
    g_vt[c * MK + r] = __float2half_rn(V[i]);
}
__global__ void combine_k(float* __restrict__ out) {
    int i = blockIdx.x * blockDim.x + threadIdx.x;  // float4 index
    if (i >= NQ * DD / 4) return;
    int row = i >> 5;
    float inv = 1.f / (g_lpart[row] + g_lpart[NQ + row]);
    float4 a = *(const float4*)&g_opart[i * 4];
    float4 b = *(const float4*)&g_opart[NQ * DD + i * 4];
    float4 o = make_float4((a.x + b.x) * inv, (a.y + b.y) * inv,
                           (a.z + b.z) * inv, (a.w + b.w) * inv);
    *(float4*)&out[i * 4] = o;
}

// ---------------- main attention kernel (warp mma.sync, fp16, 2 CTA/SM) ----------------
// dyn smem (from 1024-aligned base):
//   Qhi [64 rows][256B, chunk-swizzled]   @ 0      (16 KB)
//   buf b (b=0..1) @ 16384 + b*49152:  Khi(16K) Klo(16K) Vt(16K)
#define Q_HI 0
#define BUF0 16384
#define BUFSZ 49152
constexpr size_t SMEM_BYTES = 1024 + 16384 + 2 * 49152;   // 115712 -> 2 CTAs/SM

__device__ __forceinline__ void load_kv_tile(uint32_t buf, int c0, int tid) {
    // K hi/lo: 64 rows x 16 chunks(16B), swizzled chunk = cc ^ (r&7)
    #pragma unroll
    for (int i = 0; i < 8; i++) {
        int w = tid + i * THREADS;
        int r = w >> 4, cc = w & 15;
        cp_async16(buf + r * 256 + ((cc ^ (r & 7)) << 4),
                   g_khi + (size_t)(c0 + r) * DD + cc * 8);
    }
    #pragma unroll
    for (int i = 0; i < 8; i++) {
        int w = tid + i * THREADS;
        int r = w >> 4, cc = w & 15;
        cp_async16(buf + 16384 + r * 256 + ((cc ^ (r & 7)) << 4),
                   g_klo + (size_t)(c0 + r) * DD + cc * 8);
    }
    // Vt: 128 rows(d) x 8 chunks, swizzle cc ^ (d&7)
    #pragma unroll
    for (int i = 0; i < 8; i++) {
        int w = tid + i * THREADS;
        int d = w >> 3, cc = w & 7;
        cp_async16(buf + 32768 + d * 128 + ((cc ^ (d & 7)) << 4),
                   g_vt + (size_t)d * MK + c0 + cc * 8);
    }
}

__global__ __launch_bounds__(THREADS, 2)
void attn_mma_k() {
    extern __shared__ char smdyn[];
    uint32_t smd = (smem_u32(smdyn) + 1023u) & ~1023u;

    const int tid = threadIdx.x;
    const int wp = tid >> 5;        // 0..3 -> 16 rows each
    const int lane = tid & 31;
    const int g = lane >> 2, tt = lane & 3;
    const int m4 = lane >> 3;       // ldmatrix matrix group 0..3
    const int l7 = lane & 7;

    const int row_blk = blockIdx.x >> 1;
    const int split = blockIdx.x & 1;
    const int row0 = row_blk * BM;
    const int cbase = split * CPS;

    // ---- prologue: Q tile (64 rows) + first two KV tiles via cp.async ----
    #pragma unroll
    for (int i = 0; i < 8; i++) {
        int w = tid + i * THREADS;
        int r = w >> 4, cc = w & 15;
        cp_async16(smd + Q_HI + r * 256 + ((cc ^ (r & 7)) << 4),
                   g_qhi + (size_t)(row0 + r) * DD + cc * 8);
    }
    load_kv_tile(smd + BUF0, cbase, tid);
    CP_COMMIT();                                     // G0: Q + tile0
    load_kv_tile(smd + BUF0 + BUFSZ, cbase + BN, tid);
    CP_COMMIT();                                     // G1: tile1

    // per-lane ldmatrix address components
    const int a_row = wp * 16 + ((m4 & 1) << 3) + l7;        // Q rows for A frags (<64)
    const uint32_t a_hi = smd + Q_HI + a_row * 256;
    const int a_sw = a_row & 7;
    const int a_ms = m4 >> 1;                                 // chunk select (k-half)
    const int b_rb = ((m4 >> 1) << 3) + l7;                   // B row base within tile
    const int b_sw = b_rb & 7;
    const int b_ms = m4 & 1;

    float oa[16][4];
    #pragma unroll
    for (int i = 0; i < 16; i++)
        #pragma unroll
        for (int j = 0; j < 4; j++) oa[i][j] = 0.f;
    float l0 = 0.f, l1 = 0.f;

    const float SC = 0.12753102694653973f;  // log2(e)/sqrt(128)
    const unsigned* mrow = g_mask + (size_t)(row0 + wp * 16 + g) * WPR + (cbase >> 5);

    for (int t = 0; t < TT; t++) {
        const uint32_t buf = smd + BUF0 + (t & 1) * BUFSZ;
        CP_WAIT_1();       // tile t resident
        __syncthreads();

        // prefetch mask words: LDG latency hides under the S MMAs
        uint2 mw0 = *(const uint2*)(mrow + t * 2);
        uint2 mw1 = *(const uint2*)(mrow + 8 * WPR + t * 2);

        // ---- S = Qhi*Khi + Qhi*Klo = Qhi*K  (per warp: 16 x 64) ----
        float sc[8][4];
        #pragma unroll
        for (int i = 0; i < 8; i++)
            #pragma unroll
            for (int j = 0; j < 4; j++) sc[i][j] = 0.f;

        const uint32_t kh = buf, kl = buf + 16384;
        #pragma unroll
        for (int kc = 0; kc < 8; kc++) {
            uint32_t ah0, ah1, ah2, ah3;
            uint32_t choA = (uint32_t)(((2 * kc + a_ms) ^ a_sw) << 4);
            ldsm4(ah0, ah1, ah2, ah3, a_hi + choA);
            uint32_t choB = (uint32_t)(((2 * kc + b_ms) ^ b_sw) << 4);
            #pragma unroll
            for (int jp = 0; jp < 4; jp++) {
                uint32_t roff = (uint32_t)((jp * 16 + b_rb) * 256) + choB;
                uint32_t bh0, bh1, bh2, bh3, bl0, bl1, bl2, bl3;
                ldsm4(bh0, bh1, bh2, bh3, kh + roff);
                ldsm4(bl0, bl1, bl2, bl3, kl + roff);
                mma16816(sc[2 * jp],     ah0, ah1, ah2, ah3, bh0, bh1);
                mma16816(sc[2 * jp + 1], ah0, ah1, ah2, ah3, bh2, bh3);
                mma16816(sc[2 * jp],     ah0, ah1, ah2, ah3, bl0, bl1);
                mma16816(sc[2 * jp + 1], ah0, ah1, ah2, ah3, bl2, bl3);
            }
        }

        // ---- mask + exp2 + pack P into fp16 A-fragments ----
        uint32_t ph[4][4];
        #pragma unroll
        for (int j = 0; j < 8; j++) {
            unsigned w0 = (j < 4) ? mw0.x : mw0.y;
            unsigned w1 = (j < 4) ? mw1.x : mw1.y;
            int sh = (j & 3) * 8 + 2 * tt;
            float p00 = ((w0 >> sh) & 1u)       ? 0.f : fexp2(sc[j][0] * SC);
            float p01 = ((w0 >> (sh + 1)) & 1u) ? 0.f : fexp2(sc[j][1] * SC);
            float p10 = ((w1 >> sh) & 1u)       ? 0.f : fexp2(sc[j][2] * SC);
            float p11 = ((w1 >> (sh + 1)) & 1u) ? 0.f : fexp2(sc[j][3] * SC);
            l0 += p00 + p01;
            l1 += p10 + p11;
            __half2 h0 = __floats2half2_rn(p00, p01);
            __half2 h1 = __floats2half2_rn(p10, p11);
            int kc2 = j >> 1, hs = (j & 1) * 2;
            ph[kc2][hs]     = *(uint32_t*)&h0;
            ph[kc2][hs + 1] = *(uint32_t*)&h1;
        }

        // ---- O += P*V  (per warp: 16 x 128) ----
        const uint32_t vh = buf + 32768;
        #pragma unroll
        for (int kc2 = 0; kc2 < 4; kc2++) {
            uint32_t cho = (uint32_t)(((2 * kc2 + b_ms) ^ b_sw) << 4);
            #pragma unroll
            for (int p = 0; p < 8; p++) {
                uint32_t roff = (uint32_t)((p * 16 + b_rb) * 128) + cho;
                uint32_t vh0, vh1, vh2, vh3;
                ldsm4(vh0, vh1, vh2, vh3, vh + roff);
                mma16816(oa[2 * p],     ph[kc2][0], ph[kc2][1], ph[kc2][2], ph[kc2][3], vh0, vh1);
                mma16816(oa[2 * p + 1], ph[kc2][0], ph[kc2][1], ph[kc2][2], ph[kc2][3], vh2, vh3);
            }
        }

        __syncthreads();   // all warps done reading buf before refill
        if (t + 2 < TT)
            load_kv_tile(buf, cbase + (t + 2) * BN, tid);
        CP_COMMIT();       // (possibly empty group keeps wait_group(1) semantics)
    }

    // ---- reduce l across the 4 lanes of each row group ----
    #pragma unroll
    for (int off = 1; off < 4; off <<= 1) {
        l0 += __shfl_xor_sync(0xffffffffu, l0, off);
        l1 += __shfl_xor_sync(0xffffffffu, l1, off);
    }

    // ---- store unnormalized partial O + l ----
    {
        const int r0g = row0 + wp * 16 + g;
        float* op0 = g_opart + ((size_t)split * NQ + r0g) * DD;
        float* op1 = op0 + 8 * DD;
        #pragma unroll
        for (int dn = 0; dn < 16; dn++) {
            *(float2*)(op0 + dn * 8 + 2 * tt) = make_float2(oa[dn][0], oa[dn][1]);
            *(float2*)(op1 + dn * 8 + 2 * tt) = make_float2(oa[dn][2], oa[dn][3]);
        }
        if (tt == 0) {
            g_lpart[(size_t)split * NQ + r0g] = l0;
            g_lpart[(size_t)split * NQ + r0g + 8] = l1;
        }
    }
}

// ---------------- launcher ----------------
extern "C" void kernel_launch(void* const* d_in, const int* in_sizes, int n_in,
                              void* d_out, int out_size) {
    const float* Q  = (const float*)d_in[0];
    const float* K  = (const float*)d_in[1];
    const float* V  = (const float*)d_in[2];
    const int*   mr = (const int*)d_in[3];
    const int*   mc = (const int*)d_in[4];
    const int nmask = in_sizes[3];
    float* Out = (float*)d_out;

    cudaFuncSetAttribute(attn_mma_k, cudaFuncAttributeMaxDynamicSharedMemorySize,
                         (int)SMEM_BYTES);

    clear_mask_k<<<512, 256>>>();
    scatter_mask_k<<<(nmask + 255) / 256, 256>>>(mr, mc, nmask);
    convert_k<<<(NQ * DD + 255) / 256, 256>>>(Q, K, V);
    attn_mma_k<<<(NQ / BM) * SPLITS, THREADS, SMEM_BYTES>>>();
    combine_k<<<(NQ * DD / 4 + 255) / 256, 256>>>(Out);
}

// round 9
// speedup vs baseline: 9.8818x; 1.3087x over previous
#include <cuda_runtime.h>
#include <cuda_fp16.h>
#include <cstdint>

#define NQ 8192
#define MK 8192
#define DD 128
#define WPR 256            // mask words per row
#define BM 64
#define BN 64
#define SPLITS 2
#define CPS (MK / SPLITS)  // 4096 cols per split
#define TT (CPS / BN)      // 64 tiles per CTA
#define THREADS 128

// ---------------- device globals (no allocations allowed) ----------------
__device__ __align__(16) unsigned g_mask[NQ * WPR];                   // 8 MB bitmap
__device__ __align__(256) __half g_qh[NQ * DD];
__device__ __align__(256) __half g_kh[MK * DD];
__device__ __align__(256) __half g_vt[DD * MK];                       // V transposed [d][m]
__device__ __align__(16) float g_opart[SPLITS * NQ * DD];             // unnormalized partial O
__device__ __align__(16) float g_lpart[SPLITS * NQ];                  // partial softmax sums

// ---------------- helpers ----------------
__device__ __forceinline__ uint32_t smem_u32(const void* p) {
    uint32_t a;
    asm("{ .reg .u64 t; cvta.to.shared.u64 t, %1; cvt.u32.u64 %0, t; }" : "=r"(a) : "l"(p));
    return a;
}
__device__ __forceinline__ float fexp2(float x) {
    float y; asm("ex2.approx.ftz.f32 %0, %1;" : "=f"(y) : "f"(x)); return y;
}
__device__ __forceinline__ void cp_async16(uint32_t dst, const void* src) {
    asm volatile("cp.async.cg.shared.global [%0], [%1], 16;" :: "r"(dst), "l"(src) : "memory");
}
#define CP_COMMIT()   asm volatile("cp.async.commit_group;" ::: "memory")
#define CP_WAIT_1()   asm volatile("cp.async.wait_group 1;" ::: "memory")

__device__ __forceinline__ void ldsm4(uint32_t& r0, uint32_t& r1, uint32_t& r2, uint32_t& r3,
                                      uint32_t a) {
    asm volatile("ldmatrix.sync.aligned.m8n8.x4.shared.b16 {%0,%1,%2,%3}, [%4];"
                 : "=r"(r0), "=r"(r1), "=r"(r2), "=r"(r3) : "r"(a));
}
__device__ __forceinline__ void mma16816(float* c, uint32_t a0, uint32_t a1, uint32_t a2,
                                         uint32_t a3, uint32_t b0, uint32_t b1) {
    asm volatile("mma.sync.aligned.m16n8k16.row.col.f32.f16.f16.f32 "
                 "{%0,%1,%2,%3}, {%4,%5,%6,%7}, {%8,%9}, {%0,%1,%2,%3};"
                 : "+f"(c[0]), "+f"(c[1]), "+f"(c[2]), "+f"(c[3])
                 : "r"(a0), "r"(a1), "r"(a2), "r"(a3), "r"(b0), "r"(b1));
}

// ---------------- aux kernels ----------------
__global__ void clear_mask_k() {
    const int total = NQ * WPR;
    for (int i = blockIdx.x * blockDim.x + threadIdx.x; i < total; i += gridDim.x * blockDim.x)
        g_mask[i] = 0u;
}
__global__ void scatter_mask_k(const int* __restrict__ rows, const int* __restrict__ cols, int n) {
    int i = blockIdx.x * blockDim.x + threadIdx.x;
    if (i < n) {
        unsigned r = (unsigned)rows[i], c = (unsigned)cols[i];
        atomicOr(&g_mask[r * WPR + (c >> 5)], 1u << (c & 31u));
    }
}
__global__ void convert_k(const float* __restrict__ Q, const float* __restrict__ K,
                          const float* __restrict__ V) {
    int i = blockIdx.x * blockDim.x + threadIdx.x;
    if (i >= NQ * DD) return;
    g_qh[i] = __float2half_rn(Q[i]);
    g_kh[i] = __float2half_rn(K[i]);
    int r = i >> 7, c = i & 127;
    g_vt[c * MK + r] = __float2half_rn(V[i]);
}
__global__ void combine_k(float* __restrict__ out) {
    int i = blockIdx.x * blockDim.x + threadIdx.x;  // float4 index
    if (i >= NQ * DD / 4) return;
    int row = i >> 5;
    float inv = 1.f / (g_lpart[row] + g_lpart[NQ + row]);
    float4 a = *(const float4*)&g_opart[i * 4];
    float4 b = *(const float4*)&g_opart[NQ * DD + i * 4];
    float4 o = make_float4((a.x + b.x) * inv, (a.y + b.y) * inv,
                           (a.z + b.z) * inv, (a.w + b.w) * inv);
    *(float4*)&out[i * 4] = o;
}

// ---------------- main attention kernel (warp mma.sync, fp16, 2 CTA/SM) ----------------
// dyn smem (from 1024-aligned base):
//   Qh  [64 rows][256B, chunk-swizzled]   @ 0      (16 KB)
//   buf b (b=0..2) @ 16384 + b*32768:  Kh(16K) Vt(16K)
#define Q_HI 0
#define BUF0 16384
#define BUFSZ 32768
constexpr size_t SMEM_BYTES = 1024 + 16384 + 3 * 32768;   // 115712 -> 2 CTAs/SM

__device__ __forceinline__ void load_kv_tile(uint32_t buf, int c0, int tid) {
    // K: 64 rows x 16 chunks(16B), swizzled chunk = cc ^ (r&7)
    #pragma unroll
    for (int i = 0; i < 8; i++) {
        int w = tid + i * THREADS;
        int r = w >> 4, cc = w & 15;
        cp_async16(buf + r * 256 + ((cc ^ (r & 7)) << 4),
                   g_kh + (size_t)(c0 + r) * DD + cc * 8);
    }
    // Vt: 128 rows(d) x 8 chunks, swizzle cc ^ (d&7)
    #pragma unroll
    for (int i = 0; i < 8; i++) {
        int w = tid + i * THREADS;
        int d = w >> 3, cc = w & 7;
        cp_async16(buf + 16384 + d * 128 + ((cc ^ (d & 7)) << 4),
                   g_vt + (size_t)d * MK + c0 + cc * 8);
    }
}

__global__ __launch_bounds__(THREADS, 2)
void attn_mma_k() {
    extern __shared__ char smdyn[];
    uint32_t smd = (smem_u32(smdyn) + 1023u) & ~1023u;

    const int tid = threadIdx.x;
    const int wp = tid >> 5;        // 0..3 -> 16 rows each
    const int lane = tid & 31;
    const int g = lane >> 2, tt = lane & 3;
    const int m4 = lane >> 3;       // ldmatrix matrix group 0..3
    const int l7 = lane & 7;

    const int row_blk = blockIdx.x >> 1;
    const int split = blockIdx.x & 1;
    const int row0 = row_blk * BM;
    const int cbase = split * CPS;

    // ---- prologue: Q tile (64 rows) + first two KV tiles via cp.async ----
    #pragma unroll
    for (int i = 0; i < 8; i++) {
        int w = tid + i * THREADS;
        int r = w >> 4, cc = w & 15;
        cp_async16(smd + Q_HI + r * 256 + ((cc ^ (r & 7)) << 4),
                   g_qh + (size_t)(row0 + r) * DD + cc * 8);
    }
    load_kv_tile(smd + BUF0, cbase, tid);
    CP_COMMIT();                                     // G0: Q + tile0
    load_kv_tile(smd + BUF0 + BUFSZ, cbase + BN, tid);
    CP_COMMIT();                                     // G1: tile1

    // per-lane ldmatrix address components
    const int a_row = wp * 16 + ((m4 & 1) << 3) + l7;        // Q rows for A frags (<64)
    const uint32_t a_hi = smd + Q_HI + a_row * 256;
    const int a_sw = a_row & 7;
    const int a_ms = m4 >> 1;                                 // chunk select (k-half)
    const int b_rb = ((m4 >> 1) << 3) + l7;                   // B row base within tile
    const int b_sw = b_rb & 7;
    const int b_ms = m4 & 1;

    float oa[16][4];
    #pragma unroll
    for (int i = 0; i < 16; i++)
        #pragma unroll
        for (int j = 0; j < 4; j++) oa[i][j] = 0.f;
    float l0 = 0.f, l1 = 0.f;

    const float SC = 0.12753102694653973f;  // log2(e)/sqrt(128)
    const unsigned* mrow = g_mask + (size_t)(row0 + wp * 16 + g) * WPR + (cbase >> 5);

    // ---- wait for Q + tile0, then hoist Q A-fragments into registers ----
    CP_WAIT_1();
    __syncthreads();
    uint32_t aq[8][4];
    #pragma unroll
    for (int kc = 0; kc < 8; kc++) {
        uint32_t choA = (uint32_t)(((2 * kc + a_ms) ^ a_sw) << 4);
        ldsm4(aq[kc][0], aq[kc][1], aq[kc][2], aq[kc][3], a_hi + choA);
    }

    for (int t = 0; t < TT; t++) {
        const uint32_t buf = smd + BUF0 + (t % 3) * BUFSZ;
        CP_WAIT_1();       // tile t resident (t+1 may still be in flight)
        __syncthreads();   // all warps past PV(t-1) -> buf[(t+2)%3] (== buf[t-1]) free

        if (t + 2 < TT)
            load_kv_tile(smd + BUF0 + ((t + 2) % 3) * BUFSZ, cbase + (t + 2) * BN, tid);
        CP_COMMIT();       // always commit (possibly empty) to keep group window

        // prefetch mask words: LDG latency hides under the S MMAs
        uint2 mw0 = *(const uint2*)(mrow + t * 2);
        uint2 mw1 = *(const uint2*)(mrow + 8 * WPR + t * 2);

        // ---- S = Q*K (fp16 single pass, per warp: 16 x 64) ----
        float sc[8][4];
        #pragma unroll
        for (int i = 0; i < 8; i++)
            #pragma unroll
            for (int j = 0; j < 4; j++) sc[i][j] = 0.f;

        #pragma unroll
        for (int kc = 0; kc < 8; kc++) {
            uint32_t choB = (uint32_t)(((2 * kc + b_ms) ^ b_sw) << 4);
            #pragma unroll
            for (int jp = 0; jp < 4; jp++) {
                uint32_t roff = (uint32_t)((jp * 16 + b_rb) * 256) + choB;
                uint32_t bh0, bh1, bh2, bh3;
                ldsm4(bh0, bh1, bh2, bh3, buf + roff);
                mma16816(sc[2 * jp],     aq[kc][0], aq[kc][1], aq[kc][2], aq[kc][3], bh0, bh1);
                mma16816(sc[2 * jp + 1], aq[kc][0], aq[kc][1], aq[kc][2], aq[kc][3], bh2, bh3);
            }
        }

        // ---- mask + exp2 + pack P into fp16 A-fragments ----
        uint32_t ph[4][4];
        #pragma unroll
        for (int j = 0; j < 8; j++) {
            unsigned w0 = (j < 4) ? mw0.x : mw0.y;
            unsigned w1 = (j < 4) ? mw1.x : mw1.y;
            int sh = (j & 3) * 8 + 2 * tt;
            float p00 = ((w0 >> sh) & 1u)       ? 0.f : fexp2(sc[j][0] * SC);
            float p01 = ((w0 >> (sh + 1)) & 1u) ? 0.f : fexp2(sc[j][1] * SC);
            float p10 = ((w1 >> sh) & 1u)       ? 0.f : fexp2(sc[j][2] * SC);
            float p11 = ((w1 >> (sh + 1)) & 1u) ? 0.f : fexp2(sc[j][3] * SC);
            l0 += p00 + p01;
            l1 += p10 + p11;
            __half2 h0 = __floats2half2_rn(p00, p01);
            __half2 h1 = __floats2half2_rn(p10, p11);
            int kc2 = j >> 1, hs = (j & 1) * 2;
            ph[kc2][hs]     = *(uint32_t*)&h0;
            ph[kc2][hs + 1] = *(uint32_t*)&h1;
        }

        // ---- O += P*V  (per warp: 16 x 128) ----
        const uint32_t vh = buf + 16384;
        #pragma unroll
        for (int kc2 = 0; kc2 < 4; kc2++) {
            uint32_t cho = (uint32_t)(((2 * kc2 + b_ms) ^ b_sw) << 4);
            #pragma unroll
            for (int p = 0; p < 8; p++) {
                uint32_t roff = (uint32_t)((p * 16 + b_rb) * 128) + cho;
                uint32_t vh0, vh1, vh2, vh3;
                ldsm4(vh0, vh1, vh2, vh3, vh + roff);
                mma16816(oa[2 * p],     ph[kc2][0], ph[kc2][1], ph[kc2][2], ph[kc2][3], vh0, vh1);
                mma16816(oa[2 * p + 1], ph[kc2][0], ph[kc2][1], ph[kc2][2], ph[kc2][3], vh2, vh3);
            }
        }
    }

    // ---- reduce l across the 4 lanes of each row group ----
    #pragma unroll
    for (int off = 1; off < 4; off <<= 1) {
        l0 += __shfl_xor_sync(0xffffffffu, l0, off);
        l1 += __shfl_xor_sync(0xffffffffu, l1, off);
    }

    // ---- store unnormalized partial O + l ----
    {
        const int r0g = row0 + wp * 16 + g;
        float* op0 = g_opart + ((size_t)split * NQ + r0g) * DD;
        float* op1 = op0 + 8 * DD;
        #pragma unroll
        for (int dn = 0; dn < 16; dn++) {
            *(float2*)(op0 + dn * 8 + 2 * tt) = make_float2(oa[dn][0], oa[dn][1]);
            *(float2*)(op1 + dn * 8 + 2 * tt) = make_float2(oa[dn][2], oa[dn][3]);
        }
        if (tt == 0) {
            g_lpart[(size_t)split * NQ + r0g] = l0;
            g_lpart[(size_t)split * NQ + r0g + 8] = l1;
        }
    }
}

// ---------------- launcher ----------------
extern "C" void kernel_launch(void* const* d_in, const int* in_sizes, int n_in,
                              void* d_out, int out_size) {
    const float* Q  = (const float*)d_in[0];
    const float* K  = (const float*)d_in[1];
    const float* V  = (const float*)d_in[2];
    const int*   mr = (const int*)d_in[3];
    const int*   mc = (const int*)d_in[4];
    const int nmask = in_sizes[3];
    float* Out = (float*)d_out;

    cudaFuncSetAttribute(attn_mma_k, cudaFuncAttributeMaxDynamicSharedMemorySize,
                         (int)SMEM_BYTES);

    clear_mask_k<<<512, 256>>>();
    scatter_mask_k<<<(nmask + 255) / 256, 256>>>(mr, mc, nmask);
    convert_k<<<(NQ * DD + 255) / 256, 256>>>(Q, K, V);
    attn_mma_k<<<(NQ / BM) * SPLITS, THREADS, SMEM_BYTES>>>();
    combine_k<<<(NQ * DD / 4 + 255) / 256, 256>>>(Out);
}

// round 10
// speedup vs baseline: 11.4628x; 1.1600x over previous
#include <cuda_runtime.h>
#include <cuda_fp16.h>
#include <cstdint>

#define NQ 8192
#define MK 8192
#define DD 128
#define WPR 256            // mask words per row
#define BM 64
#define BN 64
#define SPLITS 8
#define CPS (MK / SPLITS)  // 1024 cols per split
#define TT (CPS / BN)      // 16 tiles per CTA
#define THREADS 128

// ---------------- device globals (no allocations allowed) ----------------
__device__ __align__(16) unsigned g_mask[NQ * WPR];                   // 8 MB bitmap
__device__ __align__(256) __half g_qh[NQ * DD];                       // Q * log2(e)/sqrt(d), fp16
__device__ __align__(256) __half g_kh[MK * DD];
__device__ __align__(256) __half g_vt[DD * MK];                       // V transposed [d][m]
__device__ __align__(16) float g_opart[SPLITS * NQ * DD];             // unnormalized partial O
__device__ __align__(16) float g_lpart[SPLITS * NQ];                  // partial softmax sums

// ---------------- helpers ----------------
__device__ __forceinline__ uint32_t smem_u32(const void* p) {
    uint32_t a;
    asm("{ .reg .u64 t; cvta.to.shared.u64 t, %1; cvt.u32.u64 %0, t; }" : "=r"(a) : "l"(p));
    return a;
}
__device__ __forceinline__ float fexp2(float x) {
    float y; asm("ex2.approx.ftz.f32 %0, %1;" : "=f"(y) : "f"(x)); return y;
}
__device__ __forceinline__ void cp_async16(uint32_t dst, const void* src) {
    asm volatile("cp.async.cg.shared.global [%0], [%1], 16;" :: "r"(dst), "l"(src) : "memory");
}
#define CP_COMMIT()   asm volatile("cp.async.commit_group;" ::: "memory")
#define CP_WAIT_1()   asm volatile("cp.async.wait_group 1;" ::: "memory")

__device__ __forceinline__ void ldsm4(uint32_t& r0, uint32_t& r1, uint32_t& r2, uint32_t& r3,
                                      uint32_t a) {
    asm volatile("ldmatrix.sync.aligned.m8n8.x4.shared.b16 {%0,%1,%2,%3}, [%4];"
                 : "=r"(r0), "=r"(r1), "=r"(r2), "=r"(r3) : "r"(a));
}
__device__ __forceinline__ void mma16816(float* c, uint32_t a0, uint32_t a1, uint32_t a2,
                                         uint32_t a3, uint32_t b0, uint32_t b1) {
    asm volatile("mma.sync.aligned.m16n8k16.row.col.f32.f16.f16.f32 "
                 "{%0,%1,%2,%3}, {%4,%5,%6,%7}, {%8,%9}, {%0,%1,%2,%3};"
                 : "+f"(c[0]), "+f"(c[1]), "+f"(c[2]), "+f"(c[3])
                 : "r"(a0), "r"(a1), "r"(a2), "r"(a3), "r"(b0), "r"(b1));
}

// ---------------- aux kernels ----------------
__global__ void clear_mask_k() {
    const int total = NQ * WPR;
    for (int i = blockIdx.x * blockDim.x + threadIdx.x; i < total; i += gridDim.x * blockDim.x)
        g_mask[i] = 0u;
}
__global__ void scatter_mask_k(const int* __restrict__ rows, const int* __restrict__ cols, int n) {
    int i = blockIdx.x * blockDim.x + threadIdx.x;
    if (i < n) {
        unsigned r = (unsigned)rows[i], c = (unsigned)cols[i];
        atomicOr(&g_mask[r * WPR + (c >> 5)], 1u << (c & 31u));
    }
}
__global__ void convert_qk_k(const float* __restrict__ Q, const float* __restrict__ K) {
    int i = blockIdx.x * blockDim.x + threadIdx.x;
    if (i >= NQ * DD) return;
    const float SC = 0.12753102694653973f;   // log2(e)/sqrt(128), folded into Q
    g_qh[i] = __float2half_rn(Q[i] * SC);
    g_kh[i] = __float2half_rn(K[i]);
}
// 32x32 tiled transpose V[m][d] -> g_vt[d][m], coalesced both sides
__global__ void transpose_v_k(const float* __restrict__ V) {
    __shared__ __half tile[32][33];
    int bm = blockIdx.x;          // 256 tiles along M
    int bd = blockIdx.y;          // 4 tiles along D
    int tx = threadIdx.x & 31, ty = threadIdx.x >> 5;   // 32x8
    int m0 = bm * 32, d0 = bd * 32;
    #pragma unroll
    for (int i = 0; i < 4; i++) {
        int r = ty + i * 8;
        tile[r][tx] = __float2half_rn(V[(size_t)(m0 + r) * DD + d0 + tx]);
    }
    __syncthreads();
    #pragma unroll
    for (int i = 0; i < 4; i++) {
        int r = ty + i * 8;
        g_vt[(size_t)(d0 + r) * MK + m0 + tx] = tile[tx][r];
    }
}
__global__ void combine_k(float* __restrict__ out) {
    int i = blockIdx.x * blockDim.x + threadIdx.x;  // float4 index
    if (i >= NQ * DD / 4) return;
    int row = i >> 5;
    float lsum = 0.f;
    #pragma unroll
    for (int s = 0; s < SPLITS; s++) lsum += g_lpart[s * NQ + row];
    float inv = 1.f / lsum;
    float4 acc = make_float4(0.f, 0.f, 0.f, 0.f);
    #pragma unroll
    for (int s = 0; s < SPLITS; s++) {
        float4 a = *(const float4*)&g_opart[(size_t)s * NQ * DD + i * 4];
        acc.x += a.x; acc.y += a.y; acc.z += a.z; acc.w += a.w;
    }
    *(float4*)&out[i * 4] = make_float4(acc.x * inv, acc.y * inv, acc.z * inv, acc.w * inv);
}

// ---------------- main attention kernel (warp mma.sync, fp16, 2 CTA/SM) ----------------
// dyn smem (from 1024-aligned base):
//   Qh  [64 rows][256B, chunk-swizzled]   @ 0      (16 KB)
//   buf b (b=0..2) @ 16384 + b*32768:  Kh(16K) Vt(16K)
#define Q_HI 0
#define BUF0 16384
#define BUFSZ 32768
constexpr size_t SMEM_BYTES = 1024 + 16384 + 3 * 32768;   // 115712 -> 2 CTAs/SM

__device__ __forceinline__ void load_kv_tile(uint32_t buf, int c0, int tid) {
    // K: 64 rows x 16 chunks(16B), swizzled chunk = cc ^ (r&7)
    #pragma unroll
    for (int i = 0; i < 8; i++) {
        int w = tid + i * THREADS;
        int r = w >> 4, cc = w & 15;
        cp_async16(buf + r * 256 + ((cc ^ (r & 7)) << 4),
                   g_kh + (size_t)(c0 + r) * DD + cc * 8);
    }
    // Vt: 128 rows(d) x 8 chunks, swizzle cc ^ (d&7)
    #pragma unroll
    for (int i = 0; i < 8; i++) {
        int w = tid + i * THREADS;
        int d = w >> 3, cc = w & 7;
        cp_async16(buf + 16384 + d * 128 + ((cc ^ (d & 7)) << 4),
                   g_vt + (size_t)d * MK + c0 + cc * 8);
    }
}

__global__ __launch_bounds__(THREADS, 2)
void attn_mma_k() {
    extern __shared__ char smdyn[];
    uint32_t smd = (smem_u32(smdyn) + 1023u) & ~1023u;

    const int tid = threadIdx.x;
    const int wp = tid >> 5;        // 0..3 -> 16 rows each
    const int lane = tid & 31;
    const int g = lane >> 2, tt = lane & 3;
    const int m4 = lane >> 3;       // ldmatrix matrix group 0..3
    const int l7 = lane & 7;

    const int row_blk = blockIdx.x >> 3;        // 128 row blocks
    const int split = blockIdx.x & 7;           // 8 column splits
    const int row0 = row_blk * BM;
    const int cbase = split * CPS;

    // ---- prologue: Q tile (64 rows) + first two KV tiles via cp.async ----
    #pragma unroll
    for (int i = 0; i < 8; i++) {
        int w = tid + i * THREADS;
        int r = w >> 4, cc = w & 15;
        cp_async16(smd + Q_HI + r * 256 + ((cc ^ (r & 7)) << 4),
                   g_qh + (size_t)(row0 + r) * DD + cc * 8);
    }
    load_kv_tile(smd + BUF0, cbase, tid);
    CP_COMMIT();                                     // G0: Q + tile0
    load_kv_tile(smd + BUF0 + BUFSZ, cbase + BN, tid);
    CP_COMMIT();                                     // G1: tile1

    // per-lane ldmatrix address components
    const int a_row = wp * 16 + ((m4 & 1) << 3) + l7;        // Q rows for A frags (<64)
    const uint32_t a_hi = smd + Q_HI + a_row * 256;
    const int a_sw = a_row & 7;
    const int a_ms = m4 >> 1;                                 // chunk select (k-half)
    const int b_rb = ((m4 >> 1) << 3) + l7;                   // B row base within tile
    const int b_sw = b_rb & 7;
    const int b_ms = m4 & 1;

    float oa[16][4];
    #pragma unroll
    for (int i = 0; i < 16; i++)
        #pragma unroll
        for (int j = 0; j < 4; j++) oa[i][j] = 0.f;
    float l0 = 0.f, l1 = 0.f;

    const unsigned* mrow = g_mask + (size_t)(row0 + wp * 16 + g) * WPR + (cbase >> 5);

    // ---- wait for Q + tile0, then hoist Q A-fragments into registers ----
    CP_WAIT_1();
    __syncthreads();
    uint32_t aq[8][4];
    #pragma unroll
    for (int kc = 0; kc < 8; kc++) {
        uint32_t choA = (uint32_t)(((2 * kc + a_ms) ^ a_sw) << 4);
        ldsm4(aq[kc][0], aq[kc][1], aq[kc][2], aq[kc][3], a_hi + choA);
    }

    for (int t = 0; t < TT; t++) {
        const uint32_t buf = smd + BUF0 + (t % 3) * BUFSZ;
        CP_WAIT_1();       // tile t resident (t+1 may still be in flight)
        __syncthreads();   // all warps past PV(t-1) -> buf[(t+2)%3] (== buf[t-1]) free

        if (t + 2 < TT)
            load_kv_tile(smd + BUF0 + ((t + 2) % 3) * BUFSZ, cbase + (t + 2) * BN, tid);
        CP_COMMIT();       // always commit (possibly empty) to keep group window

        // prefetch mask words: LDG latency hides under the S MMAs
        uint2 mw0 = *(const uint2*)(mrow + t * 2);
        uint2 mw1 = *(const uint2*)(mrow + 8 * WPR + t * 2);

        // ---- S = Q*K (fp16 single pass, per warp: 16 x 64; scale pre-folded) ----
        float sc[8][4];
        #pragma unroll
        for (int i = 0; i < 8; i++)
            #pragma unroll
            for (int j = 0; j < 4; j++) sc[i][j] = 0.f;

        #pragma unroll
        for (int kc = 0; kc < 8; kc++) {
            uint32_t choB = (uint32_t)(((2 * kc + b_ms) ^ b_sw) << 4);
            #pragma unroll
            for (int jp = 0; jp < 4; jp++) {
                uint32_t roff = (uint32_t)((jp * 16 + b_rb) * 256) + choB;
                uint32_t bh0, bh1, bh2, bh3;
                ldsm4(bh0, bh1, bh2, bh3, buf + roff);
                mma16816(sc[2 * jp],     aq[kc][0], aq[kc][1], aq[kc][2], aq[kc][3], bh0, bh1);
                mma16816(sc[2 * jp + 1], aq[kc][0], aq[kc][1], aq[kc][2], aq[kc][3], bh2, bh3);
            }
        }

        // ---- mask + exp2 + pack P into fp16 A-fragments ----
        uint32_t ph[4][4];
        #pragma unroll
        for (int j = 0; j < 8; j++) {
            unsigned w0 = (j < 4) ? mw0.x : mw0.y;
            unsigned w1 = (j < 4) ? mw1.x : mw1.y;
            int sh = (j & 3) * 8 + 2 * tt;
            float p00 = ((w0 >> sh) & 1u)       ? 0.f : fexp2(sc[j][0]);
            float p01 = ((w0 >> (sh + 1)) & 1u) ? 0.f : fexp2(sc[j][1]);
            float p10 = ((w1 >> sh) & 1u)       ? 0.f : fexp2(sc[j][2]);
            float p11 = ((w1 >> (sh + 1)) & 1u) ? 0.f : fexp2(sc[j][3]);
            l0 += p00 + p01;
            l1 += p10 + p11;
            __half2 h0 = __floats2half2_rn(p00, p01);
            __half2 h1 = __floats2half2_rn(p10, p11);
            int kc2 = j >> 1, hs = (j & 1) * 2;
            ph[kc2][hs]     = *(uint32_t*)&h0;
            ph[kc2][hs + 1] = *(uint32_t*)&h1;
        }

        // ---- O += P*V  (per warp: 16 x 128) ----
        const uint32_t vh = buf + 16384;
        #pragma unroll
        for (int kc2 = 0; kc2 < 4; kc2++) {
            uint32_t cho = (uint32_t)(((2 * kc2 + b_ms) ^ b_sw) << 4);
            #pragma unroll
            for (int p = 0; p < 8; p++) {
                uint32_t roff = (uint32_t)((p * 16 + b_rb) * 128) + cho;
                uint32_t vh0, vh1, vh2, vh3;
                ldsm4(vh0, vh1, vh2, vh3, vh + roff);
                mma16816(oa[2 * p],     ph[kc2][0], ph[kc2][1], ph[kc2][2], ph[kc2][3], vh0, vh1);
                mma16816(oa[2 * p + 1], ph[kc2][0], ph[kc2][1], ph[kc2][2], ph[kc2][3], vh2, vh3);
            }
        }
    }

    // ---- reduce l across the 4 lanes of each row group ----
    #pragma unroll
    for (int off = 1; off < 4; off <<= 1) {
        l0 += __shfl_xor_sync(0xffffffffu, l0, off);
        l1 += __shfl_xor_sync(0xffffffffu, l1, off);
    }

    // ---- store unnormalized partial O + l ----
    {
        const int r0g = row0 + wp * 16 + g;
        float* op0 = g_opart + ((size_t)split * NQ + r0g) * DD;
        float* op1 = op0 + 8 * DD;
        #pragma unroll
        for (int dn = 0; dn < 16; dn++) {
            *(float2*)(op0 + dn * 8 + 2 * tt) = make_float2(oa[dn][0], oa[dn][1]);
            *(float2*)(op1 + dn * 8 + 2 * tt) = make_float2(oa[dn][2], oa[dn][3]);
        }
        if (tt == 0) {
            g_lpart[(size_t)split * NQ + r0g] = l0;
            g_lpart[(size_t)split * NQ + r0g + 8] = l1;
        }
    }
}

// ---------------- launcher ----------------
extern "C" void kernel_launch(void* const* d_in, const int* in_sizes, int n_in,
                              void* d_out, int out_size) {
    const float* Q  = (const float*)d_in[0];
    const float* K  = (const float*)d_in[1];
    const float* V  = (const float*)d_in[2];
    const int*   mr = (const int*)d_in[3];
    const int*   mc = (const int*)d_in[4];
    const int nmask = in_sizes[3];
    float* Out = (float*)d_out;

    cudaFuncSetAttribute(attn_mma_k, cudaFuncAttributeMaxDynamicSharedMemorySize,
                         (int)SMEM_BYTES);

    clear_mask_k<<<512, 256>>>();
    scatter_mask_k<<<(nmask + 255) / 256, 256>>>(mr, mc, nmask);
    convert_qk_k<<<(NQ * DD + 255) / 256, 256>>>(Q, K);
    dim3 tgrid(MK / 32, DD / 32);
    transpose_v_k<<<tgrid, 256>>>(V);
    attn_mma_k<<<(NQ / BM) * SPLITS, THREADS, SMEM_BYTES>>>();
    combine_k<<<(NQ * DD / 4 + 255) / 256, 256>>>(Out);
}